// round 1
// baseline (speedup 1.0000x reference)
#include <cuda_runtime.h>
#include <cuda_bf16.h>
#include <stdint.h>

// Problem constants (fixed by the reference)
#define NNODES 50000
#define NEDGES 800000
#define KDIM   512
#define HDIM   128

// ---------------- device scratch (no allocs allowed) ----------------
__device__ float g_h[NNODES * HDIM];        // GEMM output h = x @ W   (25.6 MB, L2-resident)
__device__ int   g_cnt[NNODES];             // in-degree histogram (edges only)
__device__ int   g_off[NNODES + 1];         // CSR offsets
__device__ int   g_cursor[NNODES];          // fill cursors
__device__ int   g_srcs[NEDGES];            // CSR src lists (grouped by dst)
__device__ float g_dinv[NNODES];            // deg^-1/2 (deg = in-edges + 1 self loop)

// ---------------- packed f32x2 helpers (sm_100+) ----------------
#define PACK_F32X2(out, lo, hi) \
    asm("mov.b64 %0, {%1, %2};" : "=l"(out) : "f"(lo), "f"(hi))
#define UNPACK_F32X2(lo, hi, in) \
    asm("mov.b64 {%0, %1}, %2;" : "=f"(lo), "=f"(hi) : "l"(in))
#define FMA_F32X2(d, a, b, c) \
    asm("fma.rn.f32x2 %0, %1, %2, %3;" : "=l"(d) : "l"(a), "l"(b), "l"(c))

// ============================================================================
// Kernel 1: SGEMM  h[M,128] = x[M,512] @ W[512,128]   (fp32, f32x2 packed FMA)
// BM=128, BN=128 (full width), BK=16, 256 threads, 8x8 per thread
// ============================================================================
__global__ __launch_bounds__(256)
void gemm_kernel(const float* __restrict__ X, const float* __restrict__ W)
{
    __shared__ __align__(16) float As[16][128];  // [k][m]
    __shared__ __align__(16) float Bs[16][128];  // [k][n]

    const int block_row = blockIdx.x * 128;
    const int tid = threadIdx.x;
    const int tr  = tid >> 4;   // 0..15  (row group)
    const int tc  = tid & 15;   // 0..15  (col group)

    unsigned long long acc2[8][4] = {};  // 8 rows x 4 col-pairs, packed f32x2

    for (int k0 = 0; k0 < KDIM; k0 += 16) {
        // Load A tile: 128 rows x 16 k  (2 float4 per thread), store transposed
        #pragma unroll
        for (int i = 0; i < 2; i++) {
            int s   = tid * 2 + i;          // 0..511
            int row = s >> 2;               // 0..127
            int kk  = (s & 3) * 4;          // 0,4,8,12
            int grow = block_row + row;
            float4 v = (grow < NNODES)
                ? *(const float4*)(X + (size_t)grow * KDIM + k0 + kk)
                : make_float4(0.f, 0.f, 0.f, 0.f);
            As[kk + 0][row] = v.x;
            As[kk + 1][row] = v.y;
            As[kk + 2][row] = v.z;
            As[kk + 3][row] = v.w;
        }
        // Load B tile: 16 k-rows x 128 cols (2 float4 per thread)
        #pragma unroll
        for (int i = 0; i < 2; i++) {
            int s   = tid * 2 + i;          // 0..511
            int row = s >> 5;               // 0..15
            int cc  = (s & 31) * 4;         // 0..124
            float4 v = *(const float4*)(W + (size_t)(k0 + row) * HDIM + cc);
            *(float4*)&Bs[row][cc] = v;
        }
        __syncthreads();

        #pragma unroll
        for (int k = 0; k < 16; k++) {
            float4 a0 = *(const float4*)&As[k][tr * 8];
            float4 a1 = *(const float4*)&As[k][tr * 8 + 4];
            ulonglong2 bb0 = *(const ulonglong2*)&Bs[k][tc * 8];
            ulonglong2 bb1 = *(const ulonglong2*)&Bs[k][tc * 8 + 4];
            unsigned long long b2[4] = { bb0.x, bb0.y, bb1.x, bb1.y };
            float av[8] = { a0.x, a0.y, a0.z, a0.w, a1.x, a1.y, a1.z, a1.w };
            #pragma unroll
            for (int i = 0; i < 8; i++) {
                unsigned long long a2;
                PACK_F32X2(a2, av[i], av[i]);
                #pragma unroll
                for (int j = 0; j < 4; j++)
                    FMA_F32X2(acc2[i][j], a2, b2[j], acc2[i][j]);
            }
        }
        __syncthreads();
    }

    // Store 8x8 per thread
    #pragma unroll
    for (int i = 0; i < 8; i++) {
        int row = block_row + tr * 8 + i;
        if (row >= NNODES) continue;
        float o[8];
        #pragma unroll
        for (int j = 0; j < 4; j++)
            UNPACK_F32X2(o[2 * j], o[2 * j + 1], acc2[i][j]);
        float* dst = g_h + (size_t)row * HDIM + tc * 8;
        *(float4*)(dst)     = make_float4(o[0], o[1], o[2], o[3]);
        *(float4*)(dst + 4) = make_float4(o[4], o[5], o[6], o[7]);
    }
}

// ============================================================================
// Kernel 2: zero counters
// ============================================================================
__global__ void init_kernel()
{
    int i = blockIdx.x * blockDim.x + threadIdx.x;
    if (i < NNODES) { g_cnt[i] = 0; g_cursor[i] = 0; }
}

// ============================================================================
// Kernel 3: in-degree histogram over dst
// ============================================================================
__global__ void hist_kernel(const int* __restrict__ dst)
{
    int e = blockIdx.x * blockDim.x + threadIdx.x;
    if (e < NEDGES) atomicAdd(&g_cnt[dst[e]], 1);
}

// ============================================================================
// Kernel 4: single-block exclusive scan -> CSR offsets; also dinv = rsqrt(deg)
// 1024 threads, chunked serial + Hillis-Steele over chunk sums
// ============================================================================
__global__ void scan_kernel()
{
    __shared__ int ssum[1024];
    const int t = threadIdx.x;
    const int C = (NNODES + 1023) / 1024;   // 49
    const int lo = t * C;
    const int hi = min(lo + C, NNODES);

    // dinv (independent of scan)
    for (int i = t; i < NNODES; i += 1024)
        g_dinv[i] = rsqrtf((float)(g_cnt[i] + 1));

    int sum = 0;
    for (int i = lo; i < hi; i++) sum += g_cnt[i];
    ssum[t] = sum;
    __syncthreads();

    for (int d = 1; d < 1024; d <<= 1) {
        int v = (t >= d) ? ssum[t - d] : 0;
        __syncthreads();
        ssum[t] += v;
        __syncthreads();
    }

    int run = ssum[t] - sum;   // exclusive prefix for this chunk
    for (int i = lo; i < hi; i++) {
        g_off[i] = run;
        run += g_cnt[i];
    }
    if (t == 1023) g_off[NNODES] = run;
}

// ============================================================================
// Kernel 5: fill CSR (group edge srcs by dst)
// ============================================================================
__global__ void fill_kernel(const int* __restrict__ src, const int* __restrict__ dst)
{
    int e = blockIdx.x * blockDim.x + threadIdx.x;
    if (e >= NEDGES) return;
    int d = dst[e];
    int p = atomicAdd(&g_cursor[d], 1);
    g_srcs[g_off[d] + p] = src[e];
}

// ============================================================================
// Kernel 6: aggregate + bias + PReLU.  One warp per node, float4 per lane.
// out[n] = dinv[n] * sum_{e: dst=n} h[src(e)] * dinv[src(e)]
//        + dinv[n]^2 * h[n] + b,  then PReLU
// ============================================================================
__global__ __launch_bounds__(256)
void aggregate_kernel(const float* __restrict__ b,
                      const float* __restrict__ pw,
                      float* __restrict__ out)
{
    int gwarp = (blockIdx.x * blockDim.x + threadIdx.x) >> 5;
    int lane  = threadIdx.x & 31;
    if (gwarp >= NNODES) return;

    const float4* h4 = (const float4*)g_h;
    const int n = gwarp;

    float di = g_dinv[n];
    float4 hn = h4[(size_t)n * 32 + lane];

    float4 acc = make_float4(0.f, 0.f, 0.f, 0.f);
    int s = g_off[n];
    int e = g_off[n + 1];

    // 2-wide unroll for MLP
    int i = s;
    for (; i + 1 < e; i += 2) {
        int u0 = g_srcs[i];
        int u1 = g_srcs[i + 1];
        float w0 = g_dinv[u0];
        float w1 = g_dinv[u1];
        float4 v0 = h4[(size_t)u0 * 32 + lane];
        float4 v1 = h4[(size_t)u1 * 32 + lane];
        acc.x += v0.x * w0 + v1.x * w1;
        acc.y += v0.y * w0 + v1.y * w1;
        acc.z += v0.z * w0 + v1.z * w1;
        acc.w += v0.w * w0 + v1.w * w1;
    }
    if (i < e) {
        int u = g_srcs[i];
        float w = g_dinv[u];
        float4 v = h4[(size_t)u * 32 + lane];
        acc.x += v.x * w; acc.y += v.y * w; acc.z += v.z * w; acc.w += v.w * w;
    }

    float s2 = di * di;
    float4 bb = ((const float4*)b)[lane];
    float4 pp = ((const float4*)pw)[lane];
    float4 r;
    r.x = acc.x * di + hn.x * s2 + bb.x;
    r.y = acc.y * di + hn.y * s2 + bb.y;
    r.z = acc.z * di + hn.z * s2 + bb.z;
    r.w = acc.w * di + hn.w * s2 + bb.w;
    r.x = (r.x > 0.f) ? r.x : r.x * pp.x;
    r.y = (r.y > 0.f) ? r.y : r.y * pp.y;
    r.z = (r.z > 0.f) ? r.z : r.z * pp.z;
    r.w = (r.w > 0.f) ? r.w : r.w * pp.w;

    ((float4*)out)[(size_t)n * 32 + lane] = r;
}

// ============================================================================
// Launch
// ============================================================================
extern "C" void kernel_launch(void* const* d_in, const int* in_sizes, int n_in,
                              void* d_out, int out_size)
{
    const float* x  = (const float*)d_in[0];   // [50000, 512]
    const int*   ei = (const int*)  d_in[1];   // [2, 800000]
    const float* W  = (const float*)d_in[2];   // [512, 128]
    const float* b  = (const float*)d_in[3];   // [128]
    const float* pw = (const float*)d_in[4];   // [128]
    float* out = (float*)d_out;                // [50000, 128]

    const int* src = ei;
    const int* dst = ei + NEDGES;

    // GEMM (independent of edge preprocessing, same stream keeps order simple)
    gemm_kernel<<<(NNODES + 127) / 128, 256>>>(x, W);

    // Edge preprocessing -> CSR
    init_kernel<<<(NNODES + 255) / 256, 256>>>();
    hist_kernel<<<(NEDGES + 255) / 256, 256>>>(dst);
    scan_kernel<<<1, 1024>>>();
    fill_kernel<<<(NEDGES + 255) / 256, 256>>>(src, dst);

    // Aggregate + bias + PReLU  (one warp per node)
    aggregate_kernel<<<(NNODES * 32 + 255) / 256, 256>>>(b, pw, out);
}

// round 2
// speedup vs baseline: 1.3075x; 1.3075x over previous
#include <cuda_runtime.h>
#include <cuda_bf16.h>
#include <stdint.h>

// Problem constants (fixed by the reference)
#define NNODES 50000
#define NEDGES 800000
#define KDIM   512
#define HDIM   128

#define SCAN_BLK 256
#define N_SCAN_BLOCKS ((NNODES + SCAN_BLK - 1) / SCAN_BLK)   // 196

// ---------------- device scratch (no allocs allowed) ----------------
__device__ float g_h[NNODES * HDIM];        // GEMM output h = x @ W   (25.6 MB, L2-resident)
__device__ int   g_cnt[NNODES];             // in-degree histogram (edges only)
__device__ int   g_off[NNODES + 1];         // CSR offsets
__device__ int   g_cursor[NNODES];          // fill cursors
__device__ int   g_srcs[NEDGES];            // CSR src lists (grouped by dst)
__device__ float g_dinv[NNODES];            // deg^-1/2 (deg = in-edges + 1 self loop)
__device__ int   g_bsum[N_SCAN_BLOCKS];     // per-block scan sums

// ---------------- packed f32x2 helpers (sm_100+) ----------------
#define PACK_F32X2(out, lo, hi) \
    asm("mov.b64 %0, {%1, %2};" : "=l"(out) : "f"(lo), "f"(hi))
#define UNPACK_F32X2(lo, hi, in) \
    asm("mov.b64 {%0, %1}, %2;" : "=f"(lo), "=f"(hi) : "l"(in))
#define FMA_F32X2(d, a, b, c) \
    asm("fma.rn.f32x2 %0, %1, %2, %3;" : "=l"(d) : "l"(a), "l"(b), "l"(c))

// ============================================================================
// Kernel 1: SGEMM  h[M,128] = x[M,512] @ W[512,128]   (fp32, f32x2 packed FMA)
// BM=128, BN=128 (full width), BK=16, 256 threads, 8x8 per thread
// ============================================================================
__global__ __launch_bounds__(256)
void gemm_kernel(const float* __restrict__ X, const float* __restrict__ W)
{
    __shared__ __align__(16) float As[16][128];  // [k][m]
    __shared__ __align__(16) float Bs[16][128];  // [k][n]

    const int block_row = blockIdx.x * 128;
    const int tid = threadIdx.x;
    const int tr  = tid >> 4;   // 0..15  (row group)
    const int tc  = tid & 15;   // 0..15  (col group)

    unsigned long long acc2[8][4] = {};  // 8 rows x 4 col-pairs, packed f32x2

    for (int k0 = 0; k0 < KDIM; k0 += 16) {
        // Load A tile: 128 rows x 16 k  (2 float4 per thread), store transposed
        #pragma unroll
        for (int i = 0; i < 2; i++) {
            int s   = tid * 2 + i;          // 0..511
            int row = s >> 2;               // 0..127
            int kk  = (s & 3) * 4;          // 0,4,8,12
            int grow = block_row + row;
            float4 v = (grow < NNODES)
                ? *(const float4*)(X + (size_t)grow * KDIM + k0 + kk)
                : make_float4(0.f, 0.f, 0.f, 0.f);
            As[kk + 0][row] = v.x;
            As[kk + 1][row] = v.y;
            As[kk + 2][row] = v.z;
            As[kk + 3][row] = v.w;
        }
        // Load B tile: 16 k-rows x 128 cols (2 float4 per thread)
        #pragma unroll
        for (int i = 0; i < 2; i++) {
            int s   = tid * 2 + i;          // 0..511
            int row = s >> 5;               // 0..15
            int cc  = (s & 31) * 4;         // 0..124
            float4 v = *(const float4*)(W + (size_t)(k0 + row) * HDIM + cc);
            *(float4*)&Bs[row][cc] = v;
        }
        __syncthreads();

        #pragma unroll
        for (int k = 0; k < 16; k++) {
            float4 a0 = *(const float4*)&As[k][tr * 8];
            float4 a1 = *(const float4*)&As[k][tr * 8 + 4];
            ulonglong2 bb0 = *(const ulonglong2*)&Bs[k][tc * 8];
            ulonglong2 bb1 = *(const ulonglong2*)&Bs[k][tc * 8 + 4];
            unsigned long long b2[4] = { bb0.x, bb0.y, bb1.x, bb1.y };
            float av[8] = { a0.x, a0.y, a0.z, a0.w, a1.x, a1.y, a1.z, a1.w };
            #pragma unroll
            for (int i = 0; i < 8; i++) {
                unsigned long long a2;
                PACK_F32X2(a2, av[i], av[i]);
                #pragma unroll
                for (int j = 0; j < 4; j++)
                    FMA_F32X2(acc2[i][j], a2, b2[j], acc2[i][j]);
            }
        }
        __syncthreads();
    }

    // Store 8x8 per thread
    #pragma unroll
    for (int i = 0; i < 8; i++) {
        int row = block_row + tr * 8 + i;
        if (row >= NNODES) continue;
        float o[8];
        #pragma unroll
        for (int j = 0; j < 4; j++)
            UNPACK_F32X2(o[2 * j], o[2 * j + 1], acc2[i][j]);
        float* dst = g_h + (size_t)row * HDIM + tc * 8;
        *(float4*)(dst)     = make_float4(o[0], o[1], o[2], o[3]);
        *(float4*)(dst + 4) = make_float4(o[4], o[5], o[6], o[7]);
    }
}

// ============================================================================
// Kernel 2: zero counters
// ============================================================================
__global__ void init_kernel()
{
    int i = blockIdx.x * blockDim.x + threadIdx.x;
    if (i < NNODES) { g_cnt[i] = 0; g_cursor[i] = 0; }
}

// ============================================================================
// Kernel 3: in-degree histogram over dst
// ============================================================================
__global__ void hist_kernel(const int* __restrict__ dst)
{
    int e = blockIdx.x * blockDim.x + threadIdx.x;
    if (e < NEDGES) atomicAdd(&g_cnt[dst[e]], 1);
}

// ============================================================================
// Kernel 4a: per-block scan (256 wide) + block sums + dinv
// ============================================================================
__global__ __launch_bounds__(SCAN_BLK)
void scan_blocks_kernel()
{
    __shared__ int sh[SCAN_BLK];
    const int t = threadIdx.x;
    const int i = blockIdx.x * SCAN_BLK + t;

    int v = (i < NNODES) ? g_cnt[i] : 0;
    if (i < NNODES) g_dinv[i] = rsqrtf((float)(v + 1));

    sh[t] = v;
    __syncthreads();
    #pragma unroll
    for (int d = 1; d < SCAN_BLK; d <<= 1) {
        int u = (t >= d) ? sh[t - d] : 0;
        __syncthreads();
        sh[t] += u;
        __syncthreads();
    }
    if (i < NNODES) g_off[i] = sh[t] - v;          // block-local exclusive
    if (t == SCAN_BLK - 1) g_bsum[blockIdx.x] = sh[t];
}

// ============================================================================
// Kernel 4b: add block-prefix to each element (parallel reduce of preceding
// block sums per block — only 196 values, trivially cheap)
// ============================================================================
__global__ __launch_bounds__(SCAN_BLK)
void scan_apply_kernel()
{
    __shared__ int red[SCAN_BLK];
    const int t = threadIdx.x;
    red[t] = (t < blockIdx.x) ? g_bsum[t] : 0;     // blockIdx.x <= 195 < 256
    __syncthreads();
    #pragma unroll
    for (int d = SCAN_BLK / 2; d > 0; d >>= 1) {
        if (t < d) red[t] += red[t + d];
        __syncthreads();
    }
    const int base = red[0];
    const int i = blockIdx.x * SCAN_BLK + t;
    if (i < NNODES) g_off[i] += base;
    if (i == 0) g_off[NNODES] = NEDGES;            // total edge count is static
}

// ============================================================================
// Kernel 5: fill CSR (group edge srcs by dst)
// ============================================================================
__global__ void fill_kernel(const int* __restrict__ src, const int* __restrict__ dst)
{
    int e = blockIdx.x * blockDim.x + threadIdx.x;
    if (e >= NEDGES) return;
    int d = dst[e];
    int p = atomicAdd(&g_cursor[d], 1);
    g_srcs[g_off[d] + p] = src[e];
}

// ============================================================================
// Kernel 6: aggregate + bias + PReLU.  One warp per node, float4 per lane.
// ============================================================================
__global__ __launch_bounds__(256)
void aggregate_kernel(const float* __restrict__ b,
                      const float* __restrict__ pw,
                      float* __restrict__ out)
{
    int gwarp = (blockIdx.x * blockDim.x + threadIdx.x) >> 5;
    int lane  = threadIdx.x & 31;
    if (gwarp >= NNODES) return;

    const float4* h4 = (const float4*)g_h;
    const int n = gwarp;

    float di = g_dinv[n];
    float4 hn = h4[(size_t)n * 32 + lane];

    float4 acc = make_float4(0.f, 0.f, 0.f, 0.f);
    int s = g_off[n];
    int e = g_off[n + 1];

    int i = s;
    for (; i + 1 < e; i += 2) {
        int u0 = g_srcs[i];
        int u1 = g_srcs[i + 1];
        float w0 = g_dinv[u0];
        float w1 = g_dinv[u1];
        float4 v0 = h4[(size_t)u0 * 32 + lane];
        float4 v1 = h4[(size_t)u1 * 32 + lane];
        acc.x += v0.x * w0 + v1.x * w1;
        acc.y += v0.y * w0 + v1.y * w1;
        acc.z += v0.z * w0 + v1.z * w1;
        acc.w += v0.w * w0 + v1.w * w1;
    }
    if (i < e) {
        int u = g_srcs[i];
        float w = g_dinv[u];
        float4 v = h4[(size_t)u * 32 + lane];
        acc.x += v.x * w; acc.y += v.y * w; acc.z += v.z * w; acc.w += v.w * w;
    }

    float s2 = di * di;
    float4 bb = ((const float4*)b)[lane];
    float4 pp = ((const float4*)pw)[lane];
    float4 r;
    r.x = acc.x * di + hn.x * s2 + bb.x;
    r.y = acc.y * di + hn.y * s2 + bb.y;
    r.z = acc.z * di + hn.z * s2 + bb.z;
    r.w = acc.w * di + hn.w * s2 + bb.w;
    r.x = (r.x > 0.f) ? r.x : r.x * pp.x;
    r.y = (r.y > 0.f) ? r.y : r.y * pp.y;
    r.z = (r.z > 0.f) ? r.z : r.z * pp.z;
    r.w = (r.w > 0.f) ? r.w : r.w * pp.w;

    ((float4*)out)[(size_t)n * 32 + lane] = r;
}

// ============================================================================
// Launch: fork CSR build onto a side stream so it overlaps the GEMM.
// Stream/events are created lazily on the first (non-captured correctness)
// call and reused; fork/join via events is graph-capture legal.
// ============================================================================
extern "C" void kernel_launch(void* const* d_in, const int* in_sizes, int n_in,
                              void* d_out, int out_size)
{
    const float* x  = (const float*)d_in[0];   // [50000, 512]
    const int*   ei = (const int*)  d_in[1];   // [2, 800000]
    const float* W  = (const float*)d_in[2];   // [512, 128]
    const float* b  = (const float*)d_in[3];   // [128]
    const float* pw = (const float*)d_in[4];   // [128]
    float* out = (float*)d_out;                // [50000, 128]

    const int* src = ei;
    const int* dst = ei + NEDGES;

    static cudaStream_t s2 = nullptr;
    static cudaEvent_t evFork = nullptr, evJoin = nullptr;
    if (s2 == nullptr) {
        cudaStreamCreateWithFlags(&s2, cudaStreamNonBlocking);
        cudaEventCreateWithFlags(&evFork, cudaEventDisableTiming);
        cudaEventCreateWithFlags(&evJoin, cudaEventDisableTiming);
    }

    // Fork: CSR-build chain on s2
    cudaEventRecord(evFork, 0);
    cudaStreamWaitEvent(s2, evFork, 0);

    init_kernel<<<(NNODES + 255) / 256, 256, 0, s2>>>();
    hist_kernel<<<(NEDGES + 255) / 256, 256, 0, s2>>>(dst);
    scan_blocks_kernel<<<N_SCAN_BLOCKS, SCAN_BLK, 0, s2>>>();
    scan_apply_kernel<<<N_SCAN_BLOCKS, SCAN_BLK, 0, s2>>>();
    fill_kernel<<<(NEDGES + 255) / 256, 256, 0, s2>>>(src, dst);
    cudaEventRecord(evJoin, s2);

    // Main stream: GEMM runs concurrently with CSR build
    gemm_kernel<<<(NNODES + 127) / 128, 256>>>(x, W);

    // Join, then aggregate (needs both h and CSR)
    cudaStreamWaitEvent(0, evJoin, 0);
    aggregate_kernel<<<(NNODES * 32 + 255) / 256, 256>>>(b, pw, out);
}

// round 4
// speedup vs baseline: 1.9604x; 1.4993x over previous
#include <cuda_runtime.h>
#include <cuda_bf16.h>
#include <stdint.h>

// Problem constants (fixed by the reference)
#define NNODES 50000
#define NEDGES 800000
#define KDIM   512
#define HDIM   128

#define SCAN_BLK 256
#define N_SCAN_BLOCKS ((NNODES + SCAN_BLK - 1) / SCAN_BLK)   // 196

#define BK 32
#define KB_ITERS (KDIM / BK)           // 16
#define TILE_FLOATS (128 * BK)         // 4096 floats per (128-row x 32-k) tile
#define N_TILES ((NNODES + 127) / 128) // 391

// ---------------- device scratch (no allocs allowed) ----------------
__device__ float g_h[NNODES * HDIM];        // GEMM output h = x @ W
__device__ int   g_cnt[NNODES];
__device__ int   g_off[NNODES + 1];
__device__ int   g_cursor[NNODES];
__device__ int   g_srcs[NEDGES];
__device__ float g_dinv[NNODES];
__device__ int   g_bsum[N_SCAN_BLOCKS];
// W pre-split tf32 hi/lo, per-kb tiles of [n=128][k=32], SW128-swizzled bytes:
__device__ float g_Wh[KB_ITERS * TILE_FLOATS];
__device__ float g_Wl[KB_ITERS * TILE_FLOATS];

// ======================= PTX helpers (all baseline compute_103-safe) =======
__device__ __forceinline__ uint32_t smem_u32(const void* p) {
    uint32_t a;
    asm("{ .reg .u64 t; cvta.to.shared.u64 t, %1; cvt.u32.u64 %0, t; }"
        : "=r"(a) : "l"(p));
    return a;
}
__device__ __forceinline__ float tf32_rn(float v) {
    uint32_t u;
    asm("cvt.rna.tf32.f32 %0, %1;" : "=r"(u) : "f"(v));
    return __uint_as_float(u);
}
__device__ __forceinline__ uint32_t sw128(uint32_t off) {
    return off ^ ((off >> 3) & 0x70);
}
__device__ __forceinline__ void ldsm_x4(uint32_t& r0, uint32_t& r1,
                                        uint32_t& r2, uint32_t& r3, uint32_t addr) {
    asm volatile("ldmatrix.sync.aligned.m8n8.x4.shared.b16 {%0,%1,%2,%3}, [%4];"
        : "=r"(r0), "=r"(r1), "=r"(r2), "=r"(r3) : "r"(addr));
}
__device__ __forceinline__ void mma_tf32(float* c, uint32_t a0, uint32_t a1,
                                         uint32_t a2, uint32_t a3,
                                         uint32_t b0, uint32_t b1) {
    asm volatile(
        "mma.sync.aligned.m16n8k8.row.col.f32.tf32.tf32.f32 "
        "{%0,%1,%2,%3}, {%4,%5,%6,%7}, {%8,%9}, {%0,%1,%2,%3};"
        : "+f"(c[0]), "+f"(c[1]), "+f"(c[2]), "+f"(c[3])
        : "r"(a0), "r"(a1), "r"(a2), "r"(a3), "r"(b0), "r"(b1));
}
__device__ __forceinline__ void cp_async16(uint32_t smem_dst, const void* gsrc) {
    asm volatile("cp.async.cg.shared.global [%0], [%1], 16;"
        :: "r"(smem_dst), "l"(gsrc) : "memory");
}
#define CP_COMMIT() asm volatile("cp.async.commit_group;" ::: "memory")
#define CP_WAIT(n)  asm volatile("cp.async.wait_group %0;" :: "n"(n) : "memory")
__device__ __forceinline__ void sts128(uint32_t addr, float4 v) {
    asm volatile("st.shared.v4.f32 [%0], {%1,%2,%3,%4};"
        :: "r"(addr), "f"(v.x), "f"(v.y), "f"(v.z), "f"(v.w) : "memory");
}

// ============================================================================
// Kernel 0: pre-split W into tf32 hi/lo, per-kb [n][k] tiles, SW128-swizzled
// so the GEMM's B staging is an identity cp.async copy.
// ============================================================================
__global__ __launch_bounds__(256)
void wprep_kernel(const float* __restrict__ W)
{
    int o = blockIdx.x * blockDim.x + threadIdx.x;
    if (o >= KB_ITERS * TILE_FLOATS) return;
    int kb = o >> 12;                     // tile index
    uint32_t byte = (o & 4095) * 4;       // byte slot within tile
    uint32_t un = sw128(byte);            // involution -> original position
    int n = un >> 7;                      // 0..127
    int k = (un & 127) >> 2;              // 0..31
    float v = W[(size_t)(kb * BK + k) * HDIM + n];
    float vh = tf32_rn(v);
    g_Wh[o] = vh;
    g_Wl[o] = tf32_rn(v - vh);
}

// ============================================================================
// Kernel 1: tf32 warp-MMA GEMM (mma.sync m16n8k8), 3xTF32 compensated.
// CTA = 128x128, 256 threads (8 warps, 4x2), warp tile 32x64.
// cp.async double-buffered B, register-prefetched A.
// ============================================================================
__global__ __launch_bounds__(256, 2)
void gemm_tc_kernel(const float* __restrict__ X)
{
    extern __shared__ char dsm[];
    const uint32_t base = (smem_u32(dsm) + 1023u) & ~1023u;
    const uint32_t A_H = base;
    const uint32_t A_L = base + 16384;
    const uint32_t B_H0 = base + 32768;   // buffers: H0,L0 then H1,L1
    const uint32_t B_L0 = base + 49152;
    const uint32_t B_H1 = base + 65536;
    const uint32_t B_L1 = base + 81920;

    const int tid  = threadIdx.x;
    const int lane = tid & 31;
    const int wid  = tid >> 5;
    const int wm   = wid >> 1;            // 0..3
    const int wn   = wid & 1;             // 0..1
    const int brow = blockIdx.x * 128;

    // ---- A staging assignment: thread -> (row r, k-half h), 4 float4 ----
    const int r = tid >> 1;
    const int h = tid & 1;
    const bool rowok = (brow + r) < NNODES;
    const float4* Xrow = (const float4*)X + (size_t)(brow + r) * 128;
    // STS addresses (swizzled), q = h*4+i
    uint32_t sts_off[4];
    #pragma unroll
    for (int i = 0; i < 4; i++) {
        uint32_t q = h * 4 + i;
        sts_off[i] = (uint32_t)r * 128 + ((q ^ (r & 7)) << 4);
    }

    // ---- ldmatrix address precompute ----
    // A frags: row = wm*32 + mf*16 + (lane&15); col16B = s*2 + (lane>>4)
    uint32_t a_rb[2], a_rx[2];
    #pragma unroll
    for (int mf = 0; mf < 2; mf++) {
        uint32_t row = wm * 32 + mf * 16 + (lane & 15);
        a_rb[mf] = row * 128;
        a_rx[mf] = row & 7;
    }
    const uint32_t a_cbase = (uint32_t)(lane >> 4);
    // B frags: n = wn*64 + p*16 + ((lane>>4)<<3) + (lane&7); col16B = s*2 + ((lane>>3)&1)
    uint32_t b_rb[4], b_rx[4];
    #pragma unroll
    for (int p = 0; p < 4; p++) {
        uint32_t n = wn * 64 + p * 16 + ((lane >> 4) << 3) + (lane & 7);
        b_rb[p] = n * 128;
        b_rx[p] = n & 7;
    }
    const uint32_t b_cbase = (uint32_t)((lane >> 3) & 1);

    float acc[2][8][4];
    #pragma unroll
    for (int mf = 0; mf < 2; mf++)
        #pragma unroll
        for (int nf = 0; nf < 8; nf++)
            #pragma unroll
            for (int j = 0; j < 4; j++) acc[mf][nf][j] = 0.f;

    // ---- prologue: X kb=0 into regs, B kb=0 via cp.async ----
    float4 xr[4];
    #pragma unroll
    for (int i = 0; i < 4; i++)
        xr[i] = rowok ? Xrow[h * 4 + i] : make_float4(0.f, 0.f, 0.f, 0.f);
    #pragma unroll
    for (int i = 0; i < 4; i++) {
        int idx = tid + i * 256;
        cp_async16(B_H0 + idx * 16, g_Wh + idx * 4);
        cp_async16(B_L0 + idx * 16, g_Wl + idx * 4);
    }
    CP_COMMIT();

    for (int kb = 0; kb < KB_ITERS; kb++) {
        const uint32_t BH = (kb & 1) ? B_H1 : B_H0;
        const uint32_t BL = (kb & 1) ? B_L1 : B_L0;

        // store A tile (split hi/lo)
        #pragma unroll
        for (int i = 0; i < 4; i++) {
            float4 v = xr[i];
            float4 vh, vl;
            vh.x = tf32_rn(v.x); vl.x = tf32_rn(v.x - vh.x);
            vh.y = tf32_rn(v.y); vl.y = tf32_rn(v.y - vh.y);
            vh.z = tf32_rn(v.z); vl.z = tf32_rn(v.z - vh.z);
            vh.w = tf32_rn(v.w); vl.w = tf32_rn(v.w - vh.w);
            sts128(A_H + sts_off[i], vh);
            sts128(A_L + sts_off[i], vl);
        }

        // prefetch next tile
        if (kb + 1 < KB_ITERS) {
            const uint32_t nBH = (kb & 1) ? B_H0 : B_H1;
            const uint32_t nBL = (kb & 1) ? B_L0 : B_L1;
            const float* wh = g_Wh + (kb + 1) * TILE_FLOATS;
            const float* wl = g_Wl + (kb + 1) * TILE_FLOATS;
            #pragma unroll
            for (int i = 0; i < 4; i++) {
                int idx = tid + i * 256;
                cp_async16(nBH + idx * 16, wh + idx * 4);
                cp_async16(nBL + idx * 16, wl + idx * 4);
            }
            CP_COMMIT();
            #pragma unroll
            for (int i = 0; i < 4; i++)
                xr[i] = rowok ? Xrow[(kb + 1) * 8 + h * 4 + i]
                              : make_float4(0.f, 0.f, 0.f, 0.f);
            CP_WAIT(1);
        } else {
            CP_WAIT(0);
        }
        __syncthreads();

        // ---- compute: 4 k8-steps ----
        #pragma unroll
        for (int s = 0; s < 4; s++) {
            uint32_t ah[2][4], al[2][4];
            #pragma unroll
            for (int mf = 0; mf < 2; mf++) {
                uint32_t colu = (uint32_t)(s * 2) + a_cbase;
                uint32_t off = a_rb[mf] + ((colu ^ a_rx[mf]) << 4);
                ldsm_x4(ah[mf][0], ah[mf][1], ah[mf][2], ah[mf][3], A_H + off);
                ldsm_x4(al[mf][0], al[mf][1], al[mf][2], al[mf][3], A_L + off);
            }
            #pragma unroll
            for (int p = 0; p < 4; p++) {
                uint32_t colu = (uint32_t)(s * 2) + b_cbase;
                uint32_t off = b_rb[p] + ((colu ^ b_rx[p]) << 4);
                uint32_t bh[4], bl[4];
                ldsm_x4(bh[0], bh[1], bh[2], bh[3], BH + off);
                ldsm_x4(bl[0], bl[1], bl[2], bl[3], BL + off);
                #pragma unroll
                for (int j = 0; j < 2; j++) {
                    #pragma unroll
                    for (int mf = 0; mf < 2; mf++) {
                        float* c = acc[mf][p * 2 + j];
                        mma_tf32(c, ah[mf][0], ah[mf][1], ah[mf][2], ah[mf][3],
                                 bh[2 * j], bh[2 * j + 1]);
                        mma_tf32(c, ah[mf][0], ah[mf][1], ah[mf][2], ah[mf][3],
                                 bl[2 * j], bl[2 * j + 1]);
                        mma_tf32(c, al[mf][0], al[mf][1], al[mf][2], al[mf][3],
                                 bh[2 * j], bh[2 * j + 1]);
                    }
                }
            }
        }
        __syncthreads();
    }

    // ---- epilogue: accum regs -> g_h ----
    #pragma unroll
    for (int mf = 0; mf < 2; mf++) {
        int row0 = brow + wm * 32 + mf * 16 + (lane >> 2);
        #pragma unroll
        for (int nf = 0; nf < 8; nf++) {
            int col = wn * 64 + nf * 8 + 2 * (lane & 3);
            if (row0 < NNODES)
                *(float2*)(g_h + (size_t)row0 * HDIM + col) =
                    make_float2(acc[mf][nf][0], acc[mf][nf][1]);
            if (row0 + 8 < NNODES)
                *(float2*)(g_h + (size_t)(row0 + 8) * HDIM + col) =
                    make_float2(acc[mf][nf][2], acc[mf][nf][3]);
        }
    }
}

// ============================================================================
// CSR build kernels (unchanged)
// ============================================================================
__global__ void init_kernel()
{
    int i = blockIdx.x * blockDim.x + threadIdx.x;
    if (i < NNODES) { g_cnt[i] = 0; g_cursor[i] = 0; }
}

__global__ void hist_kernel(const int* __restrict__ dst)
{
    int e = blockIdx.x * blockDim.x + threadIdx.x;
    if (e < NEDGES) atomicAdd(&g_cnt[dst[e]], 1);
}

__global__ __launch_bounds__(SCAN_BLK)
void scan_blocks_kernel()
{
    __shared__ int sh[SCAN_BLK];
    const int t = threadIdx.x;
    const int i = blockIdx.x * SCAN_BLK + t;

    int v = (i < NNODES) ? g_cnt[i] : 0;
    if (i < NNODES) g_dinv[i] = rsqrtf((float)(v + 1));

    sh[t] = v;
    __syncthreads();
    #pragma unroll
    for (int d = 1; d < SCAN_BLK; d <<= 1) {
        int u = (t >= d) ? sh[t - d] : 0;
        __syncthreads();
        sh[t] += u;
        __syncthreads();
    }
    if (i < NNODES) g_off[i] = sh[t] - v;
    if (t == SCAN_BLK - 1) g_bsum[blockIdx.x] = sh[t];
}

__global__ __launch_bounds__(SCAN_BLK)
void scan_apply_kernel()
{
    __shared__ int red[SCAN_BLK];
    const int t = threadIdx.x;
    red[t] = (t < blockIdx.x) ? g_bsum[t] : 0;
    __syncthreads();
    #pragma unroll
    for (int d = SCAN_BLK / 2; d > 0; d >>= 1) {
        if (t < d) red[t] += red[t + d];
        __syncthreads();
    }
    const int base = red[0];
    const int i = blockIdx.x * SCAN_BLK + t;
    if (i < NNODES) g_off[i] += base;
    if (i == 0) g_off[NNODES] = NEDGES;
}

__global__ void fill_kernel(const int* __restrict__ src, const int* __restrict__ dst)
{
    int e = blockIdx.x * blockDim.x + threadIdx.x;
    if (e >= NEDGES) return;
    int d = dst[e];
    int p = atomicAdd(&g_cursor[d], 1);
    g_srcs[g_off[d] + p] = src[e];
}

// ============================================================================
// Aggregate + bias + PReLU. One warp per node, float4 per lane.
// ============================================================================
__global__ __launch_bounds__(256)
void aggregate_kernel(const float* __restrict__ b,
                      const float* __restrict__ pw,
                      float* __restrict__ out)
{
    int gwarp = (blockIdx.x * blockDim.x + threadIdx.x) >> 5;
    int lane  = threadIdx.x & 31;
    if (gwarp >= NNODES) return;

    const float4* h4 = (const float4*)g_h;
    const int n = gwarp;

    float di = g_dinv[n];
    float4 hn = h4[(size_t)n * 32 + lane];

    float4 acc = make_float4(0.f, 0.f, 0.f, 0.f);
    int s = g_off[n];
    int e = g_off[n + 1];

    int i = s;
    for (; i + 1 < e; i += 2) {
        int u0 = g_srcs[i];
        int u1 = g_srcs[i + 1];
        float w0 = g_dinv[u0];
        float w1 = g_dinv[u1];
        float4 v0 = h4[(size_t)u0 * 32 + lane];
        float4 v1 = h4[(size_t)u1 * 32 + lane];
        acc.x += v0.x * w0 + v1.x * w1;
        acc.y += v0.y * w0 + v1.y * w1;
        acc.z += v0.z * w0 + v1.z * w1;
        acc.w += v0.w * w0 + v1.w * w1;
    }
    if (i < e) {
        int u = g_srcs[i];
        float w = g_dinv[u];
        float4 v = h4[(size_t)u * 32 + lane];
        acc.x += v.x * w; acc.y += v.y * w; acc.z += v.z * w; acc.w += v.w * w;
    }

    float s2 = di * di;
    float4 bb = ((const float4*)b)[lane];
    float4 pp = ((const float4*)pw)[lane];
    float4 r;
    r.x = acc.x * di + hn.x * s2 + bb.x;
    r.y = acc.y * di + hn.y * s2 + bb.y;
    r.z = acc.z * di + hn.z * s2 + bb.z;
    r.w = acc.w * di + hn.w * s2 + bb.w;
    r.x = (r.x > 0.f) ? r.x : r.x * pp.x;
    r.y = (r.y > 0.f) ? r.y : r.y * pp.y;
    r.z = (r.z > 0.f) ? r.z : r.z * pp.z;
    r.w = (r.w > 0.f) ? r.w : r.w * pp.w;

    ((float4*)out)[(size_t)n * 32 + lane] = r;
}

// ============================================================================
// Launch
// ============================================================================
#define GEMM_DSMEM (98304 + 1024)

extern "C" void kernel_launch(void* const* d_in, const int* in_sizes, int n_in,
                              void* d_out, int out_size)
{
    const float* x  = (const float*)d_in[0];   // [50000, 512]
    const int*   ei = (const int*)  d_in[1];   // [2, 800000]
    const float* W  = (const float*)d_in[2];   // [512, 128]
    const float* b  = (const float*)d_in[3];   // [128]
    const float* pw = (const float*)d_in[4];   // [128]
    float* out = (float*)d_out;                // [50000, 128]

    const int* src = ei;
    const int* dst = ei + NEDGES;

    static cudaStream_t s2 = nullptr;
    static cudaEvent_t evFork = nullptr, evJoin = nullptr;
    if (s2 == nullptr) {
        cudaStreamCreateWithFlags(&s2, cudaStreamNonBlocking);
        cudaEventCreateWithFlags(&evFork, cudaEventDisableTiming);
        cudaEventCreateWithFlags(&evJoin, cudaEventDisableTiming);
        cudaFuncSetAttribute(gemm_tc_kernel,
                             cudaFuncAttributeMaxDynamicSharedMemorySize, GEMM_DSMEM);
    }

    // Fork: CSR-build chain on s2
    cudaEventRecord(evFork, 0);
    cudaStreamWaitEvent(s2, evFork, 0);

    init_kernel<<<(NNODES + 255) / 256, 256, 0, s2>>>();
    hist_kernel<<<(NEDGES + 255) / 256, 256, 0, s2>>>(dst);
    scan_blocks_kernel<<<N_SCAN_BLOCKS, SCAN_BLK, 0, s2>>>();
    scan_apply_kernel<<<N_SCAN_BLOCKS, SCAN_BLK, 0, s2>>>();
    fill_kernel<<<(NEDGES + 255) / 256, 256, 0, s2>>>(src, dst);
    cudaEventRecord(evJoin, s2);

    // Main stream: W split/swizzle/fraglayout, then tensor-core GEMM
    wprep_kernel<<<(KB_ITERS * TILE_FLOATS + 255) / 256, 256>>>(W);
    gemm_tc_kernel<<<N_TILES, 256, GEMM_DSMEM>>>(x);

    // Join, then aggregate (needs both h and CSR)
    cudaStreamWaitEvent(0, evJoin, 0);
    aggregate_kernel<<<(NNODES * 32 + 255) / 256, 256>>>(b, pw, out);
}

// round 5
// speedup vs baseline: 2.1433x; 1.0933x over previous
#include <cuda_runtime.h>
#include <cuda_bf16.h>
#include <stdint.h>

// Problem constants (fixed by the reference)
#define NNODES 50000
#define NEDGES 800000
#define KDIM   512
#define HDIM   128

#define SCAN_BLK 256
#define N_SCAN_BLOCKS ((NNODES + SCAN_BLK - 1) / SCAN_BLK)   // 196

#define BK 32
#define KB_ITERS (KDIM / BK)           // 16
#define TILE_FLOATS (128 * BK)         // 4096 floats per (128 x 32) tile
#define N_TILES ((NNODES + 127) / 128) // 391

// ---------------- device scratch (no allocs allowed) ----------------
__device__ float g_h[NNODES * HDIM];        // GEMM output h = x @ W
__device__ int   g_cnt[NNODES];
__device__ int   g_off[NNODES + 1];
__device__ int   g_cursor[NNODES];
__device__ int   g_srcs[NEDGES];
__device__ float g_dinv[NNODES];
__device__ int   g_bsum[N_SCAN_BLOCKS];
// W pre-split tf32 hi/lo, per-kb tiles of [n=128][k=32], SW128-swizzled bytes:
__device__ float g_Wh[KB_ITERS * TILE_FLOATS];
__device__ float g_Wl[KB_ITERS * TILE_FLOATS];

// ======================= PTX helpers (baseline compute_103-safe) ==========
__device__ __forceinline__ uint32_t smem_u32(const void* p) {
    uint32_t a;
    asm("{ .reg .u64 t; cvta.to.shared.u64 t, %1; cvt.u32.u64 %0, t; }"
        : "=r"(a) : "l"(p));
    return a;
}
__device__ __forceinline__ float tf32_rn(float v) {
    uint32_t u;
    asm("cvt.rna.tf32.f32 %0, %1;" : "=r"(u) : "f"(v));
    return __uint_as_float(u);
}
__device__ __forceinline__ uint32_t sw128(uint32_t off) {
    return off ^ ((off >> 3) & 0x70);
}
__device__ __forceinline__ void ldsm_x4(uint32_t& r0, uint32_t& r1,
                                        uint32_t& r2, uint32_t& r3, uint32_t addr) {
    asm volatile("ldmatrix.sync.aligned.m8n8.x4.shared.b16 {%0,%1,%2,%3}, [%4];"
        : "=r"(r0), "=r"(r1), "=r"(r2), "=r"(r3) : "r"(addr));
}
__device__ __forceinline__ void mma_tf32(float* c, uint32_t a0, uint32_t a1,
                                         uint32_t a2, uint32_t a3,
                                         uint32_t b0, uint32_t b1) {
    asm volatile(
        "mma.sync.aligned.m16n8k8.row.col.f32.tf32.tf32.f32 "
        "{%0,%1,%2,%3}, {%4,%5,%6,%7}, {%8,%9}, {%0,%1,%2,%3};"
        : "+f"(c[0]), "+f"(c[1]), "+f"(c[2]), "+f"(c[3])
        : "r"(a0), "r"(a1), "r"(a2), "r"(a3), "r"(b0), "r"(b1));
}
__device__ __forceinline__ void cp_async16(uint32_t smem_dst, const void* gsrc) {
    asm volatile("cp.async.cg.shared.global [%0], [%1], 16;"
        :: "r"(smem_dst), "l"(gsrc) : "memory");
}
// zfill variant: src-size 0 -> zero fill (for OOB tail rows)
__device__ __forceinline__ void cp_async16_z(uint32_t smem_dst, const void* gsrc,
                                             uint32_t srcsz) {
    asm volatile("cp.async.cg.shared.global [%0], [%1], 16, %2;"
        :: "r"(smem_dst), "l"(gsrc), "r"(srcsz) : "memory");
}
#define CP_COMMIT() asm volatile("cp.async.commit_group;" ::: "memory")
#define CP_WAIT(n)  asm volatile("cp.async.wait_group %0;" :: "n"(n) : "memory")

// ============================================================================
// Kernel 0: pre-split W into tf32 hi/lo, per-kb [n][k] tiles, SW128-swizzled
// so the GEMM's B staging is an identity cp.async copy.
// ============================================================================
__global__ __launch_bounds__(256)
void wprep_kernel(const float* __restrict__ W)
{
    int o = blockIdx.x * blockDim.x + threadIdx.x;
    if (o >= KB_ITERS * TILE_FLOATS) return;
    int kb = o >> 12;                     // tile index
    uint32_t byte = (o & 4095) * 4;       // byte slot within tile
    uint32_t un = sw128(byte);            // involution -> original position
    int n = un >> 7;                      // 0..127
    int k = (un & 127) >> 2;              // 0..31
    float v = W[(size_t)(kb * BK + k) * HDIM + n];
    float vh = tf32_rn(v);
    g_Wh[o] = vh;
    g_Wl[o] = tf32_rn(v - vh);
}

// ============================================================================
// Kernel 1: tf32 warp-MMA GEMM (mma.sync m16n8k8), 3xTF32 compensated.
// CTA = 128x128, 256 threads (8 warps 4x2), warp tile 32x64.
// A: raw X via cp.async (double buffered); hi/lo split in registers after
//    ldmatrix (mask + sub) -- no cvt chains, no STS staging, no spills.
// B: pre-split Wh/Wl via cp.async (double buffered).
// ============================================================================
__global__ __launch_bounds__(256, 2)
void gemm_tc_kernel(const float* __restrict__ X)
{
    extern __shared__ char dsm[];
    const uint32_t base = (smem_u32(dsm) + 1023u) & ~1023u;
    const uint32_t A0  = base;            // 16KB raw X tile
    const uint32_t A1  = base + 16384;
    const uint32_t BH0 = base + 32768;
    const uint32_t BL0 = base + 49152;
    const uint32_t BH1 = base + 65536;
    const uint32_t BL1 = base + 81920;

    const int tid  = threadIdx.x;
    const int lane = tid & 31;
    const int wid  = tid >> 5;
    const int wm   = wid >> 1;            // 0..3
    const int wn   = wid & 1;             // 0..1
    const int brow = blockIdx.x * 128;

    // ---- A cp.async assignment: 4 x 16B per thread ----
    uint32_t a_dst[4];                    // swizzled dst offset within A buf
    const float* a_srcb[4];               // src base (add kb*BK per stage)
    uint32_t a_sz[4];                     // 16 or 0 (zfill for OOB rows)
    #pragma unroll
    for (int i = 0; i < 4; i++) {
        int idx = tid + i * 256;          // 0..1023
        int row = idx >> 3;               // 0..127
        int q   = idx & 7;                // 16B group in row
        a_dst[i]  = (uint32_t)row * 128 + ((uint32_t)(q ^ (row & 7)) << 4);
        a_srcb[i] = X + (size_t)(brow + row) * KDIM + q * 4;
        a_sz[i]   = ((brow + row) < NNODES) ? 16u : 0u;
    }

    // ---- ldmatrix address precompute ----
    uint32_t a_rb[2], a_rx[2];
    #pragma unroll
    for (int mf = 0; mf < 2; mf++) {
        uint32_t row = wm * 32 + mf * 16 + (lane & 15);
        a_rb[mf] = row * 128;
        a_rx[mf] = row & 7;
    }
    const uint32_t a_cbase = (uint32_t)(lane >> 4);
    uint32_t b_rb[4], b_rx[4];
    #pragma unroll
    for (int p = 0; p < 4; p++) {
        uint32_t n = wn * 64 + p * 16 + ((lane >> 4) << 3) + (lane & 7);
        b_rb[p] = n * 128;
        b_rx[p] = n & 7;
    }
    const uint32_t b_cbase = (uint32_t)((lane >> 3) & 1);

    float acc[2][8][4];
    #pragma unroll
    for (int mf = 0; mf < 2; mf++)
        #pragma unroll
        for (int nf = 0; nf < 8; nf++)
            #pragma unroll
            for (int j = 0; j < 4; j++) acc[mf][nf][j] = 0.f;

    // ---- prologue: stage kb=0 ----
    #pragma unroll
    for (int i = 0; i < 4; i++)
        cp_async16_z(A0 + a_dst[i], a_srcb[i], a_sz[i]);
    #pragma unroll
    for (int i = 0; i < 4; i++) {
        int idx = tid + i * 256;
        cp_async16(BH0 + idx * 16, g_Wh + idx * 4);
        cp_async16(BL0 + idx * 16, g_Wl + idx * 4);
    }
    CP_COMMIT();

    for (int kb = 0; kb < KB_ITERS; kb++) {
        // prefetch kb+1 into the other buffers
        if (kb + 1 < KB_ITERS) {
            const uint32_t nA  = (kb & 1) ? A0 : A1;
            const uint32_t nBH = (kb & 1) ? BH0 : BH1;
            const uint32_t nBL = (kb & 1) ? BL0 : BL1;
            const float* wh = g_Wh + (kb + 1) * TILE_FLOATS;
            const float* wl = g_Wl + (kb + 1) * TILE_FLOATS;
            #pragma unroll
            for (int i = 0; i < 4; i++)
                cp_async16_z(nA + a_dst[i], a_srcb[i] + (kb + 1) * BK, a_sz[i]);
            #pragma unroll
            for (int i = 0; i < 4; i++) {
                int idx = tid + i * 256;
                cp_async16(nBH + idx * 16, wh + idx * 4);
                cp_async16(nBL + idx * 16, wl + idx * 4);
            }
            CP_COMMIT();
            CP_WAIT(1);          // current stage landed; next still in flight
        } else {
            CP_WAIT(0);
        }
        __syncthreads();

        const uint32_t A  = (kb & 1) ? A1 : A0;
        const uint32_t BH = (kb & 1) ? BH1 : BH0;
        const uint32_t BL = (kb & 1) ? BL1 : BL0;

        // ---- compute: 4 k8-steps ----
        #pragma unroll
        for (int s = 0; s < 4; s++) {
            uint32_t ah[2][4], al[2][4];
            #pragma unroll
            for (int mf = 0; mf < 2; mf++) {
                uint32_t colu = (uint32_t)(s * 2) + a_cbase;
                uint32_t off = a_rb[mf] + ((colu ^ a_rx[mf]) << 4);
                uint32_t ar[4];
                ldsm_x4(ar[0], ar[1], ar[2], ar[3], A + off);
                #pragma unroll
                for (int j = 0; j < 4; j++) {
                    uint32_t hi = ar[j] & 0xFFFFE000u;        // exact tf32 head
                    ah[mf][j] = hi;
                    al[mf][j] = __float_as_uint(
                        __uint_as_float(ar[j]) - __uint_as_float(hi));
                }
            }
            #pragma unroll
            for (int p = 0; p < 4; p++) {
                uint32_t colu = (uint32_t)(s * 2) + b_cbase;
                uint32_t off = b_rb[p] + ((colu ^ b_rx[p]) << 4);
                uint32_t bh[4], bl[4];
                ldsm_x4(bh[0], bh[1], bh[2], bh[3], BH + off);
                ldsm_x4(bl[0], bl[1], bl[2], bl[3], BL + off);
                #pragma unroll
                for (int j = 0; j < 2; j++) {
                    #pragma unroll
                    for (int mf = 0; mf < 2; mf++) {
                        float* c = acc[mf][p * 2 + j];
                        mma_tf32(c, ah[mf][0], ah[mf][1], ah[mf][2], ah[mf][3],
                                 bh[2 * j], bh[2 * j + 1]);
                        mma_tf32(c, ah[mf][0], ah[mf][1], ah[mf][2], ah[mf][3],
                                 bl[2 * j], bl[2 * j + 1]);
                        mma_tf32(c, al[mf][0], al[mf][1], al[mf][2], al[mf][3],
                                 bh[2 * j], bh[2 * j + 1]);
                    }
                }
            }
        }
        __syncthreads();
    }

    // ---- epilogue: accum regs -> g_h ----
    #pragma unroll
    for (int mf = 0; mf < 2; mf++) {
        int row0 = brow + wm * 32 + mf * 16 + (lane >> 2);
        #pragma unroll
        for (int nf = 0; nf < 8; nf++) {
            int col = wn * 64 + nf * 8 + 2 * (lane & 3);
            if (row0 < NNODES)
                *(float2*)(g_h + (size_t)row0 * HDIM + col) =
                    make_float2(acc[mf][nf][0], acc[mf][nf][1]);
            if (row0 + 8 < NNODES)
                *(float2*)(g_h + (size_t)(row0 + 8) * HDIM + col) =
                    make_float2(acc[mf][nf][2], acc[mf][nf][3]);
        }
    }
}

// ============================================================================
// CSR build kernels (unchanged)
// ============================================================================
__global__ void init_kernel()
{
    int i = blockIdx.x * blockDim.x + threadIdx.x;
    if (i < NNODES) { g_cnt[i] = 0; g_cursor[i] = 0; }
}

__global__ void hist_kernel(const int* __restrict__ dst)
{
    int e = blockIdx.x * blockDim.x + threadIdx.x;
    if (e < NEDGES) atomicAdd(&g_cnt[dst[e]], 1);
}

__global__ __launch_bounds__(SCAN_BLK)
void scan_blocks_kernel()
{
    __shared__ int sh[SCAN_BLK];
    const int t = threadIdx.x;
    const int i = blockIdx.x * SCAN_BLK + t;

    int v = (i < NNODES) ? g_cnt[i] : 0;
    if (i < NNODES) g_dinv[i] = rsqrtf((float)(v + 1));

    sh[t] = v;
    __syncthreads();
    #pragma unroll
    for (int d = 1; d < SCAN_BLK; d <<= 1) {
        int u = (t >= d) ? sh[t - d] : 0;
        __syncthreads();
        sh[t] += u;
        __syncthreads();
    }
    if (i < NNODES) g_off[i] = sh[t] - v;
    if (t == SCAN_BLK - 1) g_bsum[blockIdx.x] = sh[t];
}

__global__ __launch_bounds__(SCAN_BLK)
void scan_apply_kernel()
{
    __shared__ int red[SCAN_BLK];
    const int t = threadIdx.x;
    red[t] = (t < blockIdx.x) ? g_bsum[t] : 0;
    __syncthreads();
    #pragma unroll
    for (int d = SCAN_BLK / 2; d > 0; d >>= 1) {
        if (t < d) red[t] += red[t + d];
        __syncthreads();
    }
    const int base = red[0];
    const int i = blockIdx.x * SCAN_BLK + t;
    if (i < NNODES) g_off[i] += base;
    if (i == 0) g_off[NNODES] = NEDGES;
}

__global__ void fill_kernel(const int* __restrict__ src, const int* __restrict__ dst)
{
    int e = blockIdx.x * blockDim.x + threadIdx.x;
    if (e >= NEDGES) return;
    int d = dst[e];
    int p = atomicAdd(&g_cursor[d], 1);
    g_srcs[g_off[d] + p] = src[e];
}

// ============================================================================
// Aggregate + bias + PReLU. One warp per node, float4 per lane, 4-wide MLP.
// ============================================================================
__global__ __launch_bounds__(256)
void aggregate_kernel(const float* __restrict__ b,
                      const float* __restrict__ pw,
                      float* __restrict__ out)
{
    int gwarp = (blockIdx.x * blockDim.x + threadIdx.x) >> 5;
    int lane  = threadIdx.x & 31;
    if (gwarp >= NNODES) return;

    const float4* h4 = (const float4*)g_h;
    const int n = gwarp;

    float di = g_dinv[n];
    float4 hn = h4[(size_t)n * 32 + lane];

    float4 acc = make_float4(0.f, 0.f, 0.f, 0.f);
    int s = g_off[n];
    int e = g_off[n + 1];

    int i = s;
    for (; i + 3 < e; i += 4) {
        int u0 = g_srcs[i];
        int u1 = g_srcs[i + 1];
        int u2 = g_srcs[i + 2];
        int u3 = g_srcs[i + 3];
        float w0 = g_dinv[u0], w1 = g_dinv[u1];
        float w2 = g_dinv[u2], w3 = g_dinv[u3];
        float4 v0 = h4[(size_t)u0 * 32 + lane];
        float4 v1 = h4[(size_t)u1 * 32 + lane];
        float4 v2 = h4[(size_t)u2 * 32 + lane];
        float4 v3 = h4[(size_t)u3 * 32 + lane];
        acc.x += v0.x * w0 + v1.x * w1 + v2.x * w2 + v3.x * w3;
        acc.y += v0.y * w0 + v1.y * w1 + v2.y * w2 + v3.y * w3;
        acc.z += v0.z * w0 + v1.z * w1 + v2.z * w2 + v3.z * w3;
        acc.w += v0.w * w0 + v1.w * w1 + v2.w * w2 + v3.w * w3;
    }
    for (; i < e; i++) {
        int u = g_srcs[i];
        float w = g_dinv[u];
        float4 v = h4[(size_t)u * 32 + lane];
        acc.x += v.x * w; acc.y += v.y * w; acc.z += v.z * w; acc.w += v.w * w;
    }

    float s2 = di * di;
    float4 bb = ((const float4*)b)[lane];
    float4 pp = ((const float4*)pw)[lane];
    float4 r;
    r.x = acc.x * di + hn.x * s2 + bb.x;
    r.y = acc.y * di + hn.y * s2 + bb.y;
    r.z = acc.z * di + hn.z * s2 + bb.z;
    r.w = acc.w * di + hn.w * s2 + bb.w;
    r.x = (r.x > 0.f) ? r.x : r.x * pp.x;
    r.y = (r.y > 0.f) ? r.y : r.y * pp.y;
    r.z = (r.z > 0.f) ? r.z : r.z * pp.z;
    r.w = (r.w > 0.f) ? r.w : r.w * pp.w;

    ((float4*)out)[(size_t)n * 32 + lane] = r;
}

// ============================================================================
// Launch
// ============================================================================
#define GEMM_DSMEM (98304 + 1024)

extern "C" void kernel_launch(void* const* d_in, const int* in_sizes, int n_in,
                              void* d_out, int out_size)
{
    const float* x  = (const float*)d_in[0];   // [50000, 512]
    const int*   ei = (const int*)  d_in[1];   // [2, 800000]
    const float* W  = (const float*)d_in[2];   // [512, 128]
    const float* b  = (const float*)d_in[3];   // [128]
    const float* pw = (const float*)d_in[4];   // [128]
    float* out = (float*)d_out;                // [50000, 128]

    const int* src = ei;
    const int* dst = ei + NEDGES;

    static cudaStream_t s2 = nullptr;
    static cudaEvent_t evFork = nullptr, evJoin = nullptr;
    if (s2 == nullptr) {
        cudaStreamCreateWithFlags(&s2, cudaStreamNonBlocking);
        cudaEventCreateWithFlags(&evFork, cudaEventDisableTiming);
        cudaEventCreateWithFlags(&evJoin, cudaEventDisableTiming);
        cudaFuncSetAttribute(gemm_tc_kernel,
                             cudaFuncAttributeMaxDynamicSharedMemorySize, GEMM_DSMEM);
    }

    // Fork: CSR-build chain on s2
    cudaEventRecord(evFork, 0);
    cudaStreamWaitEvent(s2, evFork, 0);

    init_kernel<<<(NNODES + 255) / 256, 256, 0, s2>>>();
    hist_kernel<<<(NEDGES + 255) / 256, 256, 0, s2>>>(dst);
    scan_blocks_kernel<<<N_SCAN_BLOCKS, SCAN_BLK, 0, s2>>>();
    scan_apply_kernel<<<N_SCAN_BLOCKS, SCAN_BLK, 0, s2>>>();
    fill_kernel<<<(NEDGES + 255) / 256, 256, 0, s2>>>(src, dst);
    cudaEventRecord(evJoin, s2);

    // Main stream: W split/swizzle/fraglayout, then tensor-core GEMM
    wprep_kernel<<<(KB_ITERS * TILE_FLOATS + 255) / 256, 256>>>(W);
    gemm_tc_kernel<<<N_TILES, 256, GEMM_DSMEM>>>(x);

    // Join, then aggregate (needs both h and CSR)
    cudaStreamWaitEvent(0, evJoin, 0);
    aggregate_kernel<<<(NNODES * 32 + 255) / 256, 256>>>(b, pw, out);
}

// round 6
// speedup vs baseline: 2.6391x; 1.2313x over previous
#include <cuda_runtime.h>
#include <cuda_bf16.h>
#include <stdint.h>

// Problem constants (fixed by the reference)
#define NNODES 50000
#define NEDGES 800000
#define KDIM   512
#define HDIM   128

#define SCAN_BLK 256
#define N_SCAN_BLOCKS ((NNODES + SCAN_BLK - 1) / SCAN_BLK)   // 196

#define BK 32
#define KB_ITERS (KDIM / BK)           // 16
#define N_TILES ((NNODES + 127) / 128) // 391
#define WB_U32  (KB_ITERS * 4096)      // W bf16 tiles: 16 x 16KB = 64K u32

// ---------------- device scratch (no allocs allowed) ----------------
__device__ float    g_h[NNODES * HDIM];     // GEMM output h = x @ W
__device__ int      g_cnt[NNODES];
__device__ int      g_off[NNODES + 1];
__device__ int      g_cursor[NNODES];
__device__ int      g_srcs[NEDGES];
__device__ float    g_dinv[NNODES];
__device__ int      g_bsum[N_SCAN_BLOCKS];
// W pre-split bf16 hi/lo packed pairs, per-kb tiles [n=128][128B: hi k0-31 | lo k0-31],
// SW128-swizzled so GEMM B staging is identity cp.async:
__device__ uint32_t g_Wb[WB_U32];

// ======================= PTX helpers (baseline compute_103-safe) ==========
__device__ __forceinline__ uint32_t smem_u32(const void* p) {
    uint32_t a;
    asm("{ .reg .u64 t; cvta.to.shared.u64 t, %1; cvt.u32.u64 %0, t; }"
        : "=r"(a) : "l"(p));
    return a;
}
__device__ __forceinline__ uint32_t sw128(uint32_t off) {
    return off ^ ((off >> 3) & 0x70);
}
__device__ __forceinline__ void ldsm_x4(uint32_t& r0, uint32_t& r1,
                                        uint32_t& r2, uint32_t& r3, uint32_t addr) {
    asm volatile("ldmatrix.sync.aligned.m8n8.x4.shared.b16 {%0,%1,%2,%3}, [%4];"
        : "=r"(r0), "=r"(r1), "=r"(r2), "=r"(r3) : "r"(addr));
}
__device__ __forceinline__ void mma_bf16(float* c, const uint32_t* a,
                                         uint32_t b0, uint32_t b1) {
    asm volatile(
        "mma.sync.aligned.m16n8k16.row.col.f32.bf16.bf16.f32 "
        "{%0,%1,%2,%3}, {%4,%5,%6,%7}, {%8,%9}, {%0,%1,%2,%3};"
        : "+f"(c[0]), "+f"(c[1]), "+f"(c[2]), "+f"(c[3])
        : "r"(a[0]), "r"(a[1]), "r"(a[2]), "r"(a[3]), "r"(b0), "r"(b1));
}
__device__ __forceinline__ void cp_async16(uint32_t smem_dst, const void* gsrc) {
    asm volatile("cp.async.cg.shared.global [%0], [%1], 16;"
        :: "r"(smem_dst), "l"(gsrc) : "memory");
}
__device__ __forceinline__ void cp_async16_z(uint32_t smem_dst, const void* gsrc,
                                             uint32_t srcsz) {
    asm volatile("cp.async.cg.shared.global [%0], [%1], 16, %2;"
        :: "r"(smem_dst), "l"(gsrc), "r"(srcsz) : "memory");
}
#define CP_COMMIT() asm volatile("cp.async.commit_group;" ::: "memory")
#define CP_WAIT(n)  asm volatile("cp.async.wait_group %0;" :: "n"(n) : "memory")
__device__ __forceinline__ uint4 lds128(uint32_t a) {
    uint4 v;
    asm volatile("ld.shared.v4.u32 {%0,%1,%2,%3}, [%4];"
        : "=r"(v.x), "=r"(v.y), "=r"(v.z), "=r"(v.w) : "r"(a));
    return v;
}
__device__ __forceinline__ void sts128u(uint32_t a, uint4 v) {
    asm volatile("st.shared.v4.u32 [%0], {%1,%2,%3,%4};"
        :: "r"(a), "r"(v.x), "r"(v.y), "r"(v.z), "r"(v.w) : "memory");
}
// pack {lo16=bf16rn(lo), hi16=bf16rn(hi)}
__device__ __forceinline__ uint32_t bf16x2_rn(float lo, float hi) {
    uint32_t r;
    asm("cvt.rn.bf16x2.f32 %0, %1, %2;" : "=r"(r) : "f"(hi), "f"(lo));
    return r;
}
// pack truncated bf16 pair from two f32 bit patterns (high halves)
__device__ __forceinline__ uint32_t pack_hi16(uint32_t u0, uint32_t u1) {
    return __byte_perm(u0, u1, 0x7632);
}

// ============================================================================
// Kernel 0: pre-split W -> packed bf16 hi/lo pair tiles (RN split),
// [kb][n=128][128B row: hi k0-31 | lo k0-31], SW128-swizzled.
// ============================================================================
__global__ __launch_bounds__(256)
void wprep_kernel(const float* __restrict__ W)
{
    int o = blockIdx.x * blockDim.x + threadIdx.x;   // u32 slot
    if (o >= WB_U32) return;
    int kb = o >> 12;
    uint32_t byte = (o & 4095) * 4;
    uint32_t un = sw128(byte);            // involution -> logical position
    int n  = un >> 7;                     // 0..127
    int ib = un & 127;                    // byte within row
    int hi_region = (ib < 64);
    int i = (ib & 63) >> 2;               // pair index 0..15 -> k pair (2i, 2i+1)
    int k0 = kb * BK + 2 * i;
    float w0 = W[(size_t)k0 * HDIM + n];
    float w1 = W[(size_t)(k0 + 1) * HDIM + n];
    uint32_t h01 = bf16x2_rn(w0, w1);
    uint32_t val;
    if (hi_region) {
        val = h01;
    } else {
        float b0 = __uint_as_float(h01 << 16);
        float b1 = __uint_as_float(h01 & 0xFFFF0000u);
        val = bf16x2_rn(w0 - b0, w1 - b1);
    }
    g_Wb[o] = val;
}

// ============================================================================
// Kernel 1: bf16x3 compensated GEMM via mma.sync m16n8k16.
// CTA 128x128, 256 threads (8 warps 4x2), warp tile 32x64.
// A: raw f32 cp.async (double buffered) -> per-kb LDS/convert/STS into a
//    packed bf16 tile [m][128B: hi|lo] (truncation split).
// B: pre-split packed bf16 tiles via identity cp.async (double buffered).
// ============================================================================
__global__ __launch_bounds__(256, 2)
void gemm_tc_kernel(const float* __restrict__ X)
{
    extern __shared__ char dsm[];
    const uint32_t base = (smem_u32(dsm) + 1023u) & ~1023u;
    const uint32_t RA0 = base;             // raw f32 A stage, 16KB
    const uint32_t RA1 = base + 16384;
    const uint32_t AB  = base + 32768;     // packed bf16 A tile, 16KB
    const uint32_t BB0 = base + 49152;     // packed bf16 B tiles, 16KB each
    const uint32_t BB1 = base + 65536;

    const int tid  = threadIdx.x;
    const int lane = tid & 31;
    const int wid  = tid >> 5;
    const int wm   = wid >> 1;             // 0..3
    const int wn   = wid & 1;              // 0..1
    const int brow = blockIdx.x * 128;

    // ---- raw-A cp.async assignment: 4 x 16B per thread ----
    uint32_t a_dst[4];
    const float* a_srcb[4];
    uint32_t a_sz[4];
    #pragma unroll
    for (int i = 0; i < 4; i++) {
        int idx = tid + i * 256;           // 0..1023
        int row = idx >> 3;                // 0..127
        int q   = idx & 7;                 // 16B group
        a_dst[i]  = (uint32_t)row * 128 + ((uint32_t)(q ^ (row & 7)) << 4);
        a_srcb[i] = X + (size_t)(brow + row) * KDIM + q * 4;
        a_sz[i]   = ((brow + row) < NNODES) ? 16u : 0u;
    }

    // ---- convert-pass assignment: thread -> (row r, k-half h) ----
    const int cr = tid >> 1;
    const int ch = tid & 1;
    const uint32_t crx = (uint32_t)(cr & 7);
    uint32_t c_src[4], c_dst[4];
    #pragma unroll
    for (int i = 0; i < 4; i++) {
        uint32_t q = (uint32_t)(ch * 4 + i);             // raw group (k 4q..4q+3)
        c_src[i] = (uint32_t)cr * 128 + ((q ^ crx) << 4);
    }
    // bf16 tile dst groups: hi {2h, 2h+1}, lo {4+2h, 4+2h+1}
    c_dst[0] = (uint32_t)cr * 128 + (((uint32_t)(2 * ch)     ^ crx) << 4);
    c_dst[1] = (uint32_t)cr * 128 + (((uint32_t)(2 * ch + 1) ^ crx) << 4);
    c_dst[2] = (uint32_t)cr * 128 + (((uint32_t)(4 + 2 * ch)     ^ crx) << 4);
    c_dst[3] = (uint32_t)cr * 128 + (((uint32_t)(4 + 2 * ch + 1) ^ crx) << 4);

    // ---- ldmatrix address precompute ----
    uint32_t a_rb[2], a_rx[2];
    #pragma unroll
    for (int mf = 0; mf < 2; mf++) {
        uint32_t row = wm * 32 + mf * 16 + (lane & 15);
        a_rb[mf] = row * 128;
        a_rx[mf] = row & 7;
    }
    const uint32_t a_cbase = (uint32_t)(lane >> 4);
    uint32_t b_rb[4], b_rx[4];
    #pragma unroll
    for (int p = 0; p < 4; p++) {
        uint32_t n = wn * 64 + p * 16 + ((lane >> 4) << 3) + (lane & 7);
        b_rb[p] = n * 128;
        b_rx[p] = n & 7;
    }
    const uint32_t b_cbase = (uint32_t)((lane >> 3) & 1);

    float acc[2][8][4];
    #pragma unroll
    for (int mf = 0; mf < 2; mf++)
        #pragma unroll
        for (int nf = 0; nf < 8; nf++)
            #pragma unroll
            for (int j = 0; j < 4; j++) acc[mf][nf][j] = 0.f;

    // ---- prologue: stage kb=0 ----
    #pragma unroll
    for (int i = 0; i < 4; i++)
        cp_async16_z(RA0 + a_dst[i], a_srcb[i], a_sz[i]);
    #pragma unroll
    for (int i = 0; i < 4; i++) {
        int idx = tid + i * 256;
        cp_async16(BB0 + idx * 16, g_Wb + idx * 4);
    }
    CP_COMMIT();

    for (int kb = 0; kb < KB_ITERS; kb++) {
        // prefetch kb+1
        if (kb + 1 < KB_ITERS) {
            const uint32_t nRA = (kb & 1) ? RA0 : RA1;
            const uint32_t nBB = (kb & 1) ? BB0 : BB1;
            const uint32_t* wb = g_Wb + (size_t)(kb + 1) * 4096;
            #pragma unroll
            for (int i = 0; i < 4; i++)
                cp_async16_z(nRA + a_dst[i], a_srcb[i] + (kb + 1) * BK, a_sz[i]);
            #pragma unroll
            for (int i = 0; i < 4; i++) {
                int idx = tid + i * 256;
                cp_async16(nBB + idx * 16, wb + idx * 4);
            }
            CP_COMMIT();
            CP_WAIT(1);
        } else {
            CP_WAIT(0);
        }
        __syncthreads();   // RA/BB[cur] visible; AB free (prev compute done)

        const uint32_t RA = (kb & 1) ? RA1 : RA0;
        const uint32_t BB = (kb & 1) ? BB1 : BB0;

        // ---- convert raw f32 -> packed bf16 hi/lo (truncation split) ----
        {
            uint4 raw[4];
            #pragma unroll
            for (int i = 0; i < 4; i++) raw[i] = lds128(RA + c_src[i]);
            uint32_t u[16] = { raw[0].x, raw[0].y, raw[0].z, raw[0].w,
                               raw[1].x, raw[1].y, raw[1].z, raw[1].w,
                               raw[2].x, raw[2].y, raw[2].z, raw[2].w,
                               raw[3].x, raw[3].y, raw[3].z, raw[3].w };
            uint32_t hp[8], lp[8];
            #pragma unroll
            for (int i = 0; i < 8; i++) {
                uint32_t e0 = u[2 * i], e1 = u[2 * i + 1];
                hp[i] = pack_hi16(e0, e1);
                float l0 = __uint_as_float(e0) - __uint_as_float(e0 & 0xFFFF0000u);
                float l1 = __uint_as_float(e1) - __uint_as_float(e1 & 0xFFFF0000u);
                lp[i] = pack_hi16(__float_as_uint(l0), __float_as_uint(l1));
            }
            sts128u(AB + c_dst[0], make_uint4(hp[0], hp[1], hp[2], hp[3]));
            sts128u(AB + c_dst[1], make_uint4(hp[4], hp[5], hp[6], hp[7]));
            sts128u(AB + c_dst[2], make_uint4(lp[0], lp[1], lp[2], lp[3]));
            sts128u(AB + c_dst[3], make_uint4(lp[4], lp[5], lp[6], lp[7]));
        }
        __syncthreads();   // AB visible

        // ---- compute: 2 k16-steps ----
        #pragma unroll
        for (int s = 0; s < 2; s++) {
            uint32_t ah[2][4], al[2][4];
            #pragma unroll
            for (int mf = 0; mf < 2; mf++) {
                uint32_t g = (uint32_t)(s * 2) + a_cbase;
                uint32_t offh = a_rb[mf] + (((g)     ^ a_rx[mf]) << 4);
                uint32_t offl = a_rb[mf] + (((g + 4) ^ a_rx[mf]) << 4);
                ldsm_x4(ah[mf][0], ah[mf][1], ah[mf][2], ah[mf][3], AB + offh);
                ldsm_x4(al[mf][0], al[mf][1], al[mf][2], al[mf][3], AB + offl);
            }
            #pragma unroll
            for (int p = 0; p < 4; p++) {
                uint32_t g = (uint32_t)(s * 2) + b_cbase;
                uint32_t offh = b_rb[p] + (((g)     ^ b_rx[p]) << 4);
                uint32_t offl = b_rb[p] + (((g + 4) ^ b_rx[p]) << 4);
                uint32_t bh[4], bl[4];
                ldsm_x4(bh[0], bh[1], bh[2], bh[3], BB + offh);
                ldsm_x4(bl[0], bl[1], bl[2], bl[3], BB + offl);
                #pragma unroll
                for (int j = 0; j < 2; j++) {
                    #pragma unroll
                    for (int mf = 0; mf < 2; mf++) {
                        float* c = acc[mf][p * 2 + j];
                        mma_bf16(c, ah[mf], bh[2 * j], bh[2 * j + 1]);
                        mma_bf16(c, ah[mf], bl[2 * j], bl[2 * j + 1]);
                        mma_bf16(c, al[mf], bh[2 * j], bh[2 * j + 1]);
                    }
                }
            }
        }
        __syncthreads();
    }

    // ---- epilogue: accum regs -> g_h ----
    #pragma unroll
    for (int mf = 0; mf < 2; mf++) {
        int row0 = brow + wm * 32 + mf * 16 + (lane >> 2);
        #pragma unroll
        for (int nf = 0; nf < 8; nf++) {
            int col = wn * 64 + nf * 8 + 2 * (lane & 3);
            if (row0 < NNODES)
                *(float2*)(g_h + (size_t)row0 * HDIM + col) =
                    make_float2(acc[mf][nf][0], acc[mf][nf][1]);
            if (row0 + 8 < NNODES)
                *(float2*)(g_h + (size_t)(row0 + 8) * HDIM + col) =
                    make_float2(acc[mf][nf][2], acc[mf][nf][3]);
        }
    }
}

// ============================================================================
// CSR build kernels (unchanged)
// ============================================================================
__global__ void init_kernel()
{
    int i = blockIdx.x * blockDim.x + threadIdx.x;
    if (i < NNODES) { g_cnt[i] = 0; g_cursor[i] = 0; }
}

__global__ void hist_kernel(const int* __restrict__ dst)
{
    int e = blockIdx.x * blockDim.x + threadIdx.x;
    if (e < NEDGES) atomicAdd(&g_cnt[dst[e]], 1);
}

__global__ __launch_bounds__(SCAN_BLK)
void scan_blocks_kernel()
{
    __shared__ int sh[SCAN_BLK];
    const int t = threadIdx.x;
    const int i = blockIdx.x * SCAN_BLK + t;

    int v = (i < NNODES) ? g_cnt[i] : 0;
    if (i < NNODES) g_dinv[i] = rsqrtf((float)(v + 1));

    sh[t] = v;
    __syncthreads();
    #pragma unroll
    for (int d = 1; d < SCAN_BLK; d <<= 1) {
        int u = (t >= d) ? sh[t - d] : 0;
        __syncthreads();
        sh[t] += u;
        __syncthreads();
    }
    if (i < NNODES) g_off[i] = sh[t] - v;
    if (t == SCAN_BLK - 1) g_bsum[blockIdx.x] = sh[t];
}

__global__ __launch_bounds__(SCAN_BLK)
void scan_apply_kernel()
{
    __shared__ int red[SCAN_BLK];
    const int t = threadIdx.x;
    red[t] = (t < blockIdx.x) ? g_bsum[t] : 0;
    __syncthreads();
    #pragma unroll
    for (int d = SCAN_BLK / 2; d > 0; d >>= 1) {
        if (t < d) red[t] += red[t + d];
        __syncthreads();
    }
    const int base = red[0];
    const int i = blockIdx.x * SCAN_BLK + t;
    if (i < NNODES) g_off[i] += base;
    if (i == 0) g_off[NNODES] = NEDGES;
}

__global__ void fill_kernel(const int* __restrict__ src, const int* __restrict__ dst)
{
    int e = blockIdx.x * blockDim.x + threadIdx.x;
    if (e >= NEDGES) return;
    int d = dst[e];
    int p = atomicAdd(&g_cursor[d], 1);
    g_srcs[g_off[d] + p] = src[e];
}

// ============================================================================
// Aggregate + bias + PReLU. One warp per node, float4 per lane, 4-wide MLP.
// ============================================================================
__global__ __launch_bounds__(256)
void aggregate_kernel(const float* __restrict__ b,
                      const float* __restrict__ pw,
                      float* __restrict__ out)
{
    int gwarp = (blockIdx.x * blockDim.x + threadIdx.x) >> 5;
    int lane  = threadIdx.x & 31;
    if (gwarp >= NNODES) return;

    const float4* h4 = (const float4*)g_h;
    const int n = gwarp;

    float di = g_dinv[n];
    float4 hn = h4[(size_t)n * 32 + lane];

    float4 acc = make_float4(0.f, 0.f, 0.f, 0.f);
    int s = g_off[n];
    int e = g_off[n + 1];

    int i = s;
    for (; i + 3 < e; i += 4) {
        int u0 = g_srcs[i];
        int u1 = g_srcs[i + 1];
        int u2 = g_srcs[i + 2];
        int u3 = g_srcs[i + 3];
        float w0 = g_dinv[u0], w1 = g_dinv[u1];
        float w2 = g_dinv[u2], w3 = g_dinv[u3];
        float4 v0 = h4[(size_t)u0 * 32 + lane];
        float4 v1 = h4[(size_t)u1 * 32 + lane];
        float4 v2 = h4[(size_t)u2 * 32 + lane];
        float4 v3 = h4[(size_t)u3 * 32 + lane];
        acc.x += v0.x * w0 + v1.x * w1 + v2.x * w2 + v3.x * w3;
        acc.y += v0.y * w0 + v1.y * w1 + v2.y * w2 + v3.y * w3;
        acc.z += v0.z * w0 + v1.z * w1 + v2.z * w2 + v3.z * w3;
        acc.w += v0.w * w0 + v1.w * w1 + v2.w * w2 + v3.w * w3;
    }
    for (; i < e; i++) {
        int u = g_srcs[i];
        float w = g_dinv[u];
        float4 v = h4[(size_t)u * 32 + lane];
        acc.x += v.x * w; acc.y += v.y * w; acc.z += v.z * w; acc.w += v.w * w;
    }

    float s2 = di * di;
    float4 bb = ((const float4*)b)[lane];
    float4 pp = ((const float4*)pw)[lane];
    float4 r;
    r.x = acc.x * di + hn.x * s2 + bb.x;
    r.y = acc.y * di + hn.y * s2 + bb.y;
    r.z = acc.z * di + hn.z * s2 + bb.z;
    r.w = acc.w * di + hn.w * s2 + bb.w;
    r.x = (r.x > 0.f) ? r.x : r.x * pp.x;
    r.y = (r.y > 0.f) ? r.y : r.y * pp.y;
    r.z = (r.z > 0.f) ? r.z : r.z * pp.z;
    r.w = (r.w > 0.f) ? r.w : r.w * pp.w;

    ((float4*)out)[(size_t)n * 32 + lane] = r;
}

// ============================================================================
// Launch
// ============================================================================
#define GEMM_DSMEM (81920 + 1024)

extern "C" void kernel_launch(void* const* d_in, const int* in_sizes, int n_in,
                              void* d_out, int out_size)
{
    const float* x  = (const float*)d_in[0];   // [50000, 512]
    const int*   ei = (const int*)  d_in[1];   // [2, 800000]
    const float* W  = (const float*)d_in[2];   // [512, 128]
    const float* b  = (const float*)d_in[3];   // [128]
    const float* pw = (const float*)d_in[4];   // [128]
    float* out = (float*)d_out;                // [50000, 128]

    const int* src = ei;
    const int* dst = ei + NEDGES;

    static cudaStream_t s2 = nullptr;
    static cudaEvent_t evFork = nullptr, evJoin = nullptr;
    if (s2 == nullptr) {
        cudaStreamCreateWithFlags(&s2, cudaStreamNonBlocking);
        cudaEventCreateWithFlags(&evFork, cudaEventDisableTiming);
        cudaEventCreateWithFlags(&evJoin, cudaEventDisableTiming);
        cudaFuncSetAttribute(gemm_tc_kernel,
                             cudaFuncAttributeMaxDynamicSharedMemorySize, GEMM_DSMEM);
    }

    // Fork: CSR-build chain on s2
    cudaEventRecord(evFork, 0);
    cudaStreamWaitEvent(s2, evFork, 0);

    init_kernel<<<(NNODES + 255) / 256, 256, 0, s2>>>();
    hist_kernel<<<(NEDGES + 255) / 256, 256, 0, s2>>>(dst);
    scan_blocks_kernel<<<N_SCAN_BLOCKS, SCAN_BLK, 0, s2>>>();
    scan_apply_kernel<<<N_SCAN_BLOCKS, SCAN_BLK, 0, s2>>>();
    fill_kernel<<<(NEDGES + 255) / 256, 256, 0, s2>>>(src, dst);
    cudaEventRecord(evJoin, s2);

    // Main stream: W split/pack, then bf16x3 tensor-core GEMM
    wprep_kernel<<<(WB_U32 + 255) / 256, 256>>>(W);
    gemm_tc_kernel<<<N_TILES, 256, GEMM_DSMEM>>>(x);

    // Join, then aggregate (needs both h and CSR)
    cudaStreamWaitEvent(0, evJoin, 0);
    aggregate_kernel<<<(NNODES * 32 + 255) / 256, 256>>>(b, pw, out);
}

// round 7
// speedup vs baseline: 2.7615x; 1.0464x over previous
#include <cuda_runtime.h>
#include <cuda_bf16.h>
#include <cuda_fp16.h>
#include <stdint.h>

// Problem constants (fixed by the reference)
#define NNODES 50000
#define NEDGES 800000
#define KDIM   512
#define HDIM   128

#define SCAN_BLK 256
#define N_SCAN_BLOCKS ((NNODES + SCAN_BLK - 1) / SCAN_BLK)   // 196

#define BK 32
#define KB_ITERS (KDIM / BK)           // 16
#define N_TILES ((NNODES + 127) / 128) // 391
#define WB_U32  (KB_ITERS * 4096)      // W bf16 tiles: 16 x 16KB = 64K u32

// ---------------- device scratch (no allocs allowed) ----------------
__device__ uint32_t g_h2[NNODES * 64];      // h = x @ W, fp16 half2-packed (12.8 MB)
__device__ int      g_cnt[NNODES];
__device__ int      g_off[NNODES + 1];
__device__ int      g_cursor[NNODES];
__device__ int      g_srcs[NEDGES];
__device__ float    g_dinv[NNODES];
__device__ int      g_bsum[N_SCAN_BLOCKS];
// W pre-split bf16 hi/lo packed pairs, per-kb tiles [n=128][128B: hi k0-31 | lo k0-31],
// SW128-swizzled so GEMM B staging is identity cp.async:
__device__ uint32_t g_Wb[WB_U32];

// ======================= PTX helpers (baseline compute_103-safe) ==========
__device__ __forceinline__ uint32_t smem_u32(const void* p) {
    uint32_t a;
    asm("{ .reg .u64 t; cvta.to.shared.u64 t, %1; cvt.u32.u64 %0, t; }"
        : "=r"(a) : "l"(p));
    return a;
}
__device__ __forceinline__ uint32_t sw128(uint32_t off) {
    return off ^ ((off >> 3) & 0x70);
}
__device__ __forceinline__ void ldsm_x4(uint32_t& r0, uint32_t& r1,
                                        uint32_t& r2, uint32_t& r3, uint32_t addr) {
    asm volatile("ldmatrix.sync.aligned.m8n8.x4.shared.b16 {%0,%1,%2,%3}, [%4];"
        : "=r"(r0), "=r"(r1), "=r"(r2), "=r"(r3) : "r"(addr));
}
__device__ __forceinline__ void mma_bf16(float* c, const uint32_t* a,
                                         uint32_t b0, uint32_t b1) {
    asm volatile(
        "mma.sync.aligned.m16n8k16.row.col.f32.bf16.bf16.f32 "
        "{%0,%1,%2,%3}, {%4,%5,%6,%7}, {%8,%9}, {%0,%1,%2,%3};"
        : "+f"(c[0]), "+f"(c[1]), "+f"(c[2]), "+f"(c[3])
        : "r"(a[0]), "r"(a[1]), "r"(a[2]), "r"(a[3]), "r"(b0), "r"(b1));
}
__device__ __forceinline__ void cp_async16(uint32_t smem_dst, const void* gsrc) {
    asm volatile("cp.async.cg.shared.global [%0], [%1], 16;"
        :: "r"(smem_dst), "l"(gsrc) : "memory");
}
__device__ __forceinline__ void cp_async16_z(uint32_t smem_dst, const void* gsrc,
                                             uint32_t srcsz) {
    asm volatile("cp.async.cg.shared.global [%0], [%1], 16, %2;"
        :: "r"(smem_dst), "l"(gsrc), "r"(srcsz) : "memory");
}
#define CP_COMMIT() asm volatile("cp.async.commit_group;" ::: "memory")
#define CP_WAIT(n)  asm volatile("cp.async.wait_group %0;" :: "n"(n) : "memory")
__device__ __forceinline__ uint4 lds128(uint32_t a) {
    uint4 v;
    asm volatile("ld.shared.v4.u32 {%0,%1,%2,%3}, [%4];"
        : "=r"(v.x), "=r"(v.y), "=r"(v.z), "=r"(v.w) : "r"(a));
    return v;
}
__device__ __forceinline__ void sts128u(uint32_t a, uint4 v) {
    asm volatile("st.shared.v4.u32 [%0], {%1,%2,%3,%4};"
        :: "r"(a), "r"(v.x), "r"(v.y), "r"(v.z), "r"(v.w) : "memory");
}
__device__ __forceinline__ uint32_t bf16x2_rn(float lo, float hi) {
    uint32_t r;
    asm("cvt.rn.bf16x2.f32 %0, %1, %2;" : "=r"(r) : "f"(hi), "f"(lo));
    return r;
}
__device__ __forceinline__ uint32_t pack_hi16(uint32_t u0, uint32_t u1) {
    return __byte_perm(u0, u1, 0x7632);
}

// ============================================================================
// Kernel 0: pre-split W -> packed bf16 hi/lo pair tiles (RN split),
// [kb][n=128][128B row: hi k0-31 | lo k0-31], SW128-swizzled.
// ============================================================================
__global__ __launch_bounds__(256)
void wprep_kernel(const float* __restrict__ W)
{
    int o = blockIdx.x * blockDim.x + threadIdx.x;   // u32 slot
    if (o >= WB_U32) return;
    int kb = o >> 12;
    uint32_t byte = (o & 4095) * 4;
    uint32_t un = sw128(byte);            // involution -> logical position
    int n  = un >> 7;                     // 0..127
    int ib = un & 127;                    // byte within row
    int hi_region = (ib < 64);
    int i = (ib & 63) >> 2;               // pair index 0..15 -> k pair (2i, 2i+1)
    int k0 = kb * BK + 2 * i;
    float w0 = W[(size_t)k0 * HDIM + n];
    float w1 = W[(size_t)(k0 + 1) * HDIM + n];
    uint32_t h01 = bf16x2_rn(w0, w1);
    uint32_t val;
    if (hi_region) {
        val = h01;
    } else {
        float b0 = __uint_as_float(h01 << 16);
        float b1 = __uint_as_float(h01 & 0xFFFF0000u);
        val = bf16x2_rn(w0 - b0, w1 - b1);
    }
    g_Wb[o] = val;
}

// ============================================================================
// Kernel 1: bf16x3 compensated GEMM via mma.sync m16n8k16.
// CTA 128x128, 256 threads (8 warps 4x2), warp tile 32x64.
// Pipeline: prefetch kb+1 issued AFTER convert-sync so it overlaps compute;
// 2 syncthreads per kb. AB single-buffered (top-of-loop sync protects it).
// Epilogue packs fp16 (half2) into g_h2.
// ============================================================================
__global__ __launch_bounds__(256, 2)
void gemm_tc_kernel(const float* __restrict__ X)
{
    extern __shared__ char dsm[];
    const uint32_t base = (smem_u32(dsm) + 1023u) & ~1023u;
    const uint32_t RA0 = base;             // raw f32 A stages
    const uint32_t RA1 = base + 16384;
    const uint32_t BB0 = base + 32768;     // packed bf16 B stages
    const uint32_t BB1 = base + 49152;
    const uint32_t AB  = base + 65536;     // packed bf16 A tile

    const int tid  = threadIdx.x;
    const int lane = tid & 31;
    const int wid  = tid >> 5;
    const int wm   = wid >> 1;             // 0..3
    const int wn   = wid & 1;              // 0..1
    const int brow = blockIdx.x * 128;

    // ---- raw-A cp.async assignment: 4 x 16B per thread ----
    uint32_t a_dst[4];
    const float* a_srcb[4];
    uint32_t a_sz[4];
    #pragma unroll
    for (int i = 0; i < 4; i++) {
        int idx = tid + i * 256;           // 0..1023
        int row = idx >> 3;                // 0..127
        int q   = idx & 7;                 // 16B group
        a_dst[i]  = (uint32_t)row * 128 + ((uint32_t)(q ^ (row & 7)) << 4);
        a_srcb[i] = X + (size_t)(brow + row) * KDIM + q * 4;
        a_sz[i]   = ((brow + row) < NNODES) ? 16u : 0u;
    }

    // ---- convert-pass assignment: thread -> (row r, k-half h) ----
    const int cr = tid >> 1;
    const int ch = tid & 1;
    const uint32_t crx = (uint32_t)(cr & 7);
    uint32_t c_src[4], c_dst[4];
    #pragma unroll
    for (int i = 0; i < 4; i++) {
        uint32_t q = (uint32_t)(ch * 4 + i);
        c_src[i] = (uint32_t)cr * 128 + ((q ^ crx) << 4);
    }
    c_dst[0] = (uint32_t)cr * 128 + (((uint32_t)(2 * ch)     ^ crx) << 4);
    c_dst[1] = (uint32_t)cr * 128 + (((uint32_t)(2 * ch + 1) ^ crx) << 4);
    c_dst[2] = (uint32_t)cr * 128 + (((uint32_t)(4 + 2 * ch)     ^ crx) << 4);
    c_dst[3] = (uint32_t)cr * 128 + (((uint32_t)(4 + 2 * ch + 1) ^ crx) << 4);

    // ---- ldmatrix address precompute ----
    uint32_t a_rb[2], a_rx[2];
    #pragma unroll
    for (int mf = 0; mf < 2; mf++) {
        uint32_t row = wm * 32 + mf * 16 + (lane & 15);
        a_rb[mf] = row * 128;
        a_rx[mf] = row & 7;
    }
    const uint32_t a_cbase = (uint32_t)(lane >> 4);
    uint32_t b_rb[4], b_rx[4];
    #pragma unroll
    for (int p = 0; p < 4; p++) {
        uint32_t n = wn * 64 + p * 16 + ((lane >> 4) << 3) + (lane & 7);
        b_rb[p] = n * 128;
        b_rx[p] = n & 7;
    }
    const uint32_t b_cbase = (uint32_t)((lane >> 3) & 1);

    float acc[2][8][4];
    #pragma unroll
    for (int mf = 0; mf < 2; mf++)
        #pragma unroll
        for (int nf = 0; nf < 8; nf++)
            #pragma unroll
            for (int j = 0; j < 4; j++) acc[mf][nf][j] = 0.f;

    // ---- prologue: stage kb=0 ----
    #pragma unroll
    for (int i = 0; i < 4; i++)
        cp_async16_z(RA0 + a_dst[i], a_srcb[i], a_sz[i]);
    #pragma unroll
    for (int i = 0; i < 4; i++) {
        int idx = tid + i * 256;
        cp_async16(BB0 + idx * 16, g_Wb + idx * 4);
    }
    CP_COMMIT();

    for (int kb = 0; kb < KB_ITERS; kb++) {
        CP_WAIT(0);
        __syncthreads();   // RA/BB[cur] visible; AB free; prev compute done

        const uint32_t RA = (kb & 1) ? RA1 : RA0;
        const uint32_t BB = (kb & 1) ? BB1 : BB0;

        // ---- convert raw f32 -> packed bf16 hi/lo (truncation split) ----
        {
            uint4 raw[4];
            #pragma unroll
            for (int i = 0; i < 4; i++) raw[i] = lds128(RA + c_src[i]);
            uint32_t u[16] = { raw[0].x, raw[0].y, raw[0].z, raw[0].w,
                               raw[1].x, raw[1].y, raw[1].z, raw[1].w,
                               raw[2].x, raw[2].y, raw[2].z, raw[2].w,
                               raw[3].x, raw[3].y, raw[3].z, raw[3].w };
            uint32_t hp[8], lp[8];
            #pragma unroll
            for (int i = 0; i < 8; i++) {
                uint32_t e0 = u[2 * i], e1 = u[2 * i + 1];
                hp[i] = pack_hi16(e0, e1);
                float l0 = __uint_as_float(e0) - __uint_as_float(e0 & 0xFFFF0000u);
                float l1 = __uint_as_float(e1) - __uint_as_float(e1 & 0xFFFF0000u);
                lp[i] = pack_hi16(__float_as_uint(l0), __float_as_uint(l1));
            }
            sts128u(AB + c_dst[0], make_uint4(hp[0], hp[1], hp[2], hp[3]));
            sts128u(AB + c_dst[1], make_uint4(hp[4], hp[5], hp[6], hp[7]));
            sts128u(AB + c_dst[2], make_uint4(lp[0], lp[1], lp[2], lp[3]));
            sts128u(AB + c_dst[3], make_uint4(lp[4], lp[5], lp[6], lp[7]));
        }
        __syncthreads();   // AB visible; RA[cur] reads done

        // ---- prefetch kb+1 (overlaps with compute below) ----
        if (kb + 1 < KB_ITERS) {
            const uint32_t nRA = (kb & 1) ? RA0 : RA1;
            const uint32_t nBB = (kb & 1) ? BB0 : BB1;
            const uint32_t* wb = g_Wb + (size_t)(kb + 1) * 4096;
            #pragma unroll
            for (int i = 0; i < 4; i++)
                cp_async16_z(nRA + a_dst[i], a_srcb[i] + (kb + 1) * BK, a_sz[i]);
            #pragma unroll
            for (int i = 0; i < 4; i++) {
                int idx = tid + i * 256;
                cp_async16(nBB + idx * 16, wb + idx * 4);
            }
            CP_COMMIT();
        }

        // ---- compute: 2 k16-steps ----
        #pragma unroll
        for (int s = 0; s < 2; s++) {
            uint32_t ah[2][4], al[2][4];
            #pragma unroll
            for (int mf = 0; mf < 2; mf++) {
                uint32_t g = (uint32_t)(s * 2) + a_cbase;
                uint32_t offh = a_rb[mf] + (((g)     ^ a_rx[mf]) << 4);
                uint32_t offl = a_rb[mf] + (((g + 4) ^ a_rx[mf]) << 4);
                ldsm_x4(ah[mf][0], ah[mf][1], ah[mf][2], ah[mf][3], AB + offh);
                ldsm_x4(al[mf][0], al[mf][1], al[mf][2], al[mf][3], AB + offl);
            }
            #pragma unroll
            for (int p = 0; p < 4; p++) {
                uint32_t g = (uint32_t)(s * 2) + b_cbase;
                uint32_t offh = b_rb[p] + (((g)     ^ b_rx[p]) << 4);
                uint32_t offl = b_rb[p] + (((g + 4) ^ b_rx[p]) << 4);
                uint32_t bh[4], bl[4];
                ldsm_x4(bh[0], bh[1], bh[2], bh[3], BB + offh);
                ldsm_x4(bl[0], bl[1], bl[2], bl[3], BB + offl);
                #pragma unroll
                for (int j = 0; j < 2; j++) {
                    #pragma unroll
                    for (int mf = 0; mf < 2; mf++) {
                        float* c = acc[mf][p * 2 + j];
                        mma_bf16(c, ah[mf], bh[2 * j], bh[2 * j + 1]);
                        mma_bf16(c, ah[mf], bl[2 * j], bl[2 * j + 1]);
                        mma_bf16(c, al[mf], bh[2 * j], bh[2 * j + 1]);
                    }
                }
            }
        }
    }

    // ---- epilogue: accum regs -> g_h2 (fp16 half2-packed) ----
    half2* H2 = (half2*)g_h2;
    #pragma unroll
    for (int mf = 0; mf < 2; mf++) {
        int row0 = brow + wm * 32 + mf * 16 + (lane >> 2);
        #pragma unroll
        for (int nf = 0; nf < 8; nf++) {
            int c2 = wn * 32 + nf * 4 + (lane & 3);   // half2 column index
            if (row0 < NNODES)
                H2[(size_t)row0 * 64 + c2] =
                    __floats2half2_rn(acc[mf][nf][0], acc[mf][nf][1]);
            if (row0 + 8 < NNODES)
                H2[(size_t)(row0 + 8) * 64 + c2] =
                    __floats2half2_rn(acc[mf][nf][2], acc[mf][nf][3]);
        }
    }
}

// ============================================================================
// CSR build kernels (unchanged)
// ============================================================================
__global__ void init_kernel()
{
    int i = blockIdx.x * blockDim.x + threadIdx.x;
    if (i < NNODES) { g_cnt[i] = 0; g_cursor[i] = 0; }
}

__global__ void hist_kernel(const int* __restrict__ dst)
{
    int e = blockIdx.x * blockDim.x + threadIdx.x;
    if (e < NEDGES) atomicAdd(&g_cnt[dst[e]], 1);
}

__global__ __launch_bounds__(SCAN_BLK)
void scan_blocks_kernel()
{
    __shared__ int sh[SCAN_BLK];
    const int t = threadIdx.x;
    const int i = blockIdx.x * SCAN_BLK + t;

    int v = (i < NNODES) ? g_cnt[i] : 0;
    if (i < NNODES) g_dinv[i] = rsqrtf((float)(v + 1));

    sh[t] = v;
    __syncthreads();
    #pragma unroll
    for (int d = 1; d < SCAN_BLK; d <<= 1) {
        int u = (t >= d) ? sh[t - d] : 0;
        __syncthreads();
        sh[t] += u;
        __syncthreads();
    }
    if (i < NNODES) g_off[i] = sh[t] - v;
    if (t == SCAN_BLK - 1) g_bsum[blockIdx.x] = sh[t];
}

__global__ __launch_bounds__(SCAN_BLK)
void scan_apply_kernel()
{
    __shared__ int red[SCAN_BLK];
    const int t = threadIdx.x;
    red[t] = (t < blockIdx.x) ? g_bsum[t] : 0;
    __syncthreads();
    #pragma unroll
    for (int d = SCAN_BLK / 2; d > 0; d >>= 1) {
        if (t < d) red[t] += red[t + d];
        __syncthreads();
    }
    const int base = red[0];
    const int i = blockIdx.x * SCAN_BLK + t;
    if (i < NNODES) g_off[i] += base;
    if (i == 0) g_off[NNODES] = NEDGES;
}

__global__ void fill_kernel(const int* __restrict__ src, const int* __restrict__ dst)
{
    int e = blockIdx.x * blockDim.x + threadIdx.x;
    if (e >= NEDGES) return;
    int d = dst[e];
    int p = atomicAdd(&g_cursor[d], 1);
    g_srcs[g_off[d] + p] = src[e];
}

// ============================================================================
// Aggregate + bias + PReLU. One warp per node; each lane owns 4 channels
// (one uint2 = 4 fp16 values). Gather traffic halved vs fp32.
// ============================================================================
__device__ __forceinline__ float4 h4_at(const uint2* h2, int node, int lane)
{
    uint2 v = h2[(size_t)node * 32 + lane];
    float2 f = __half22float2(*(const half2*)&v.x);
    float2 g = __half22float2(*(const half2*)&v.y);
    return make_float4(f.x, f.y, g.x, g.y);
}

__global__ __launch_bounds__(256)
void aggregate_kernel(const float* __restrict__ b,
                      const float* __restrict__ pw,
                      float* __restrict__ out)
{
    int gwarp = (blockIdx.x * blockDim.x + threadIdx.x) >> 5;
    int lane  = threadIdx.x & 31;
    if (gwarp >= NNODES) return;

    const uint2* h2 = (const uint2*)g_h2;
    const int n = gwarp;

    float di = g_dinv[n];
    float4 hn = h4_at(h2, n, lane);

    float4 acc = make_float4(0.f, 0.f, 0.f, 0.f);
    int s = g_off[n];
    int e = g_off[n + 1];

    int i = s;
    for (; i + 3 < e; i += 4) {
        int u0 = g_srcs[i];
        int u1 = g_srcs[i + 1];
        int u2 = g_srcs[i + 2];
        int u3 = g_srcs[i + 3];
        float w0 = g_dinv[u0], w1 = g_dinv[u1];
        float w2 = g_dinv[u2], w3 = g_dinv[u3];
        float4 v0 = h4_at(h2, u0, lane);
        float4 v1 = h4_at(h2, u1, lane);
        float4 v2 = h4_at(h2, u2, lane);
        float4 v3 = h4_at(h2, u3, lane);
        acc.x += v0.x * w0 + v1.x * w1 + v2.x * w2 + v3.x * w3;
        acc.y += v0.y * w0 + v1.y * w1 + v2.y * w2 + v3.y * w3;
        acc.z += v0.z * w0 + v1.z * w1 + v2.z * w2 + v3.z * w3;
        acc.w += v0.w * w0 + v1.w * w1 + v2.w * w2 + v3.w * w3;
    }
    for (; i < e; i++) {
        int u = g_srcs[i];
        float w = g_dinv[u];
        float4 v = h4_at(h2, u, lane);
        acc.x += v.x * w; acc.y += v.y * w; acc.z += v.z * w; acc.w += v.w * w;
    }

    float s2 = di * di;
    float4 bb = ((const float4*)b)[lane];
    float4 pp = ((const float4*)pw)[lane];
    float4 r;
    r.x = acc.x * di + hn.x * s2 + bb.x;
    r.y = acc.y * di + hn.y * s2 + bb.y;
    r.z = acc.z * di + hn.z * s2 + bb.z;
    r.w = acc.w * di + hn.w * s2 + bb.w;
    r.x = (r.x > 0.f) ? r.x : r.x * pp.x;
    r.y = (r.y > 0.f) ? r.y : r.y * pp.y;
    r.z = (r.z > 0.f) ? r.z : r.z * pp.z;
    r.w = (r.w > 0.f) ? r.w : r.w * pp.w;

    ((float4*)out)[(size_t)n * 32 + lane] = r;
}

// ============================================================================
// Launch
// ============================================================================
#define GEMM_DSMEM (81920 + 1024)

extern "C" void kernel_launch(void* const* d_in, const int* in_sizes, int n_in,
                              void* d_out, int out_size)
{
    const float* x  = (const float*)d_in[0];   // [50000, 512]
    const int*   ei = (const int*)  d_in[1];   // [2, 800000]
    const float* W  = (const float*)d_in[2];   // [512, 128]
    const float* b  = (const float*)d_in[3];   // [128]
    const float* pw = (const float*)d_in[4];   // [128]
    float* out = (float*)d_out;                // [50000, 128]

    const int* src = ei;
    const int* dst = ei + NEDGES;

    static cudaStream_t s2 = nullptr;
    static cudaEvent_t evFork = nullptr, evJoin = nullptr;
    if (s2 == nullptr) {
        cudaStreamCreateWithFlags(&s2, cudaStreamNonBlocking);
        cudaEventCreateWithFlags(&evFork, cudaEventDisableTiming);
        cudaEventCreateWithFlags(&evJoin, cudaEventDisableTiming);
        cudaFuncSetAttribute(gemm_tc_kernel,
                             cudaFuncAttributeMaxDynamicSharedMemorySize, GEMM_DSMEM);
    }

    // Fork: CSR-build chain on s2
    cudaEventRecord(evFork, 0);
    cudaStreamWaitEvent(s2, evFork, 0);

    init_kernel<<<(NNODES + 255) / 256, 256, 0, s2>>>();
    hist_kernel<<<(NEDGES + 255) / 256, 256, 0, s2>>>(dst);
    scan_blocks_kernel<<<N_SCAN_BLOCKS, SCAN_BLK, 0, s2>>>();
    scan_apply_kernel<<<N_SCAN_BLOCKS, SCAN_BLK, 0, s2>>>();
    fill_kernel<<<(NEDGES + 255) / 256, 256, 0, s2>>>(src, dst);
    cudaEventRecord(evJoin, s2);

    // Main stream: W split/pack, then bf16x3 tensor-core GEMM
    wprep_kernel<<<(WB_U32 + 255) / 256, 256>>>(W);
    gemm_tc_kernel<<<N_TILES, 256, GEMM_DSMEM>>>(x);

    // Join, then aggregate (needs both h and CSR)
    cudaStreamWaitEvent(0, evJoin, 0);
    aggregate_kernel<<<(NNODES * 32 + 255) / 256, 256>>>(b, pw, out);
}

// round 8
// speedup vs baseline: 3.1244x; 1.1314x over previous
#include <cuda_runtime.h>
#include <cuda_bf16.h>
#include <cuda_fp16.h>
#include <stdint.h>

// Problem constants (fixed by the reference)
#define NNODES 50000
#define NEDGES 800000
#define KDIM   512
#define HDIM   128

#define SCAN_BLK 256
#define N_SCAN_BLOCKS ((NNODES + SCAN_BLK - 1) / SCAN_BLK)   // 196

#define BK 32
#define KB_ITERS (KDIM / BK)           // 16
#define N_TILES ((NNODES + 127) / 128) // 391
#define WB_U32  (KB_ITERS * 2048)      // W fp16 tiles: 16 x 8KB = 32K u32

// ---------------- device scratch (no allocs allowed) ----------------
__device__ uint32_t g_h2[NNODES * 64];      // h = x @ W, fp16 half2-packed (12.8 MB)
__device__ int      g_cnt[NNODES];
__device__ int      g_off[NNODES + 1];
__device__ int      g_cursor[NNODES];
__device__ int      g_srcs[NEDGES];
__device__ float    g_dinv[NNODES];
__device__ int      g_bsum[N_SCAN_BLOCKS];
// W as fp16, per-kb tiles [n=128][64B row: k0-31], SW64-swizzled so the GEMM
// B staging is an identity cp.async copy:
__device__ uint32_t g_Wb[WB_U32];

// ======================= PTX helpers (baseline compute_103-safe) ==========
__device__ __forceinline__ uint32_t smem_u32(const void* p) {
    uint32_t a;
    asm("{ .reg .u64 t; cvta.to.shared.u64 t, %1; cvt.u32.u64 %0, t; }"
        : "=r"(a) : "l"(p));
    return a;
}
__device__ __forceinline__ uint32_t sw64(uint32_t off) {   // 64B-row swizzle
    return off ^ ((off >> 3) & 0x30);
}
__device__ __forceinline__ void ldsm_x4(uint32_t& r0, uint32_t& r1,
                                        uint32_t& r2, uint32_t& r3, uint32_t addr) {
    asm volatile("ldmatrix.sync.aligned.m8n8.x4.shared.b16 {%0,%1,%2,%3}, [%4];"
        : "=r"(r0), "=r"(r1), "=r"(r2), "=r"(r3) : "r"(addr));
}
__device__ __forceinline__ void mma_fp16(float* c, const uint32_t* a,
                                         uint32_t b0, uint32_t b1) {
    asm volatile(
        "mma.sync.aligned.m16n8k16.row.col.f32.f16.f16.f32 "
        "{%0,%1,%2,%3}, {%4,%5,%6,%7}, {%8,%9}, {%0,%1,%2,%3};"
        : "+f"(c[0]), "+f"(c[1]), "+f"(c[2]), "+f"(c[3])
        : "r"(a[0]), "r"(a[1]), "r"(a[2]), "r"(a[3]), "r"(b0), "r"(b1));
}
__device__ __forceinline__ void cp_async16(uint32_t smem_dst, const void* gsrc) {
    asm volatile("cp.async.cg.shared.global [%0], [%1], 16;"
        :: "r"(smem_dst), "l"(gsrc) : "memory");
}
__device__ __forceinline__ void cp_async16_z(uint32_t smem_dst, const void* gsrc,
                                             uint32_t srcsz) {
    asm volatile("cp.async.cg.shared.global [%0], [%1], 16, %2;"
        :: "r"(smem_dst), "l"(gsrc), "r"(srcsz) : "memory");
}
#define CP_COMMIT() asm volatile("cp.async.commit_group;" ::: "memory")
#define CP_WAIT(n)  asm volatile("cp.async.wait_group %0;" :: "n"(n) : "memory")
__device__ __forceinline__ uint4 lds128(uint32_t a) {
    uint4 v;
    asm volatile("ld.shared.v4.u32 {%0,%1,%2,%3}, [%4];"
        : "=r"(v.x), "=r"(v.y), "=r"(v.z), "=r"(v.w) : "r"(a));
    return v;
}
__device__ __forceinline__ void sts128u(uint32_t a, uint4 v) {
    asm volatile("st.shared.v4.u32 [%0], {%1,%2,%3,%4};"
        :: "r"(a), "r"(v.x), "r"(v.y), "r"(v.z), "r"(v.w) : "memory");
}
// pack {lo16=fp16rn(lo), hi16=fp16rn(hi)}
__device__ __forceinline__ uint32_t f16x2_rn(float lo, float hi) {
    uint32_t r;
    asm("cvt.rn.f16x2.f32 %0, %1, %2;" : "=r"(r) : "f"(hi), "f"(lo));
    return r;
}

// ============================================================================
// Kernel 0: W -> fp16 tiles, per-kb [n=128][64B: k0-31], SW64-swizzled.
// ============================================================================
__global__ __launch_bounds__(256)
void wprep_kernel(const float* __restrict__ W)
{
    int o = blockIdx.x * blockDim.x + threadIdx.x;   // u32 slot
    if (o >= WB_U32) return;
    int kb = o >> 11;
    uint32_t byte = (o & 2047) * 4;
    uint32_t un = sw64(byte);             // involution -> logical position
    int n = un >> 6;                      // 0..127
    int i = (un & 63) >> 2;               // k-pair index 0..15
    int k0 = kb * BK + 2 * i;
    float w0 = W[(size_t)k0 * HDIM + n];
    float w1 = W[(size_t)(k0 + 1) * HDIM + n];
    g_Wb[o] = f16x2_rn(w0, w1);
}

// ============================================================================
// Kernel 1: fp16 GEMM via mma.sync m16n8k16 (f32 accumulate).
// CTA 128x128, 256 threads (8 warps 4x2), warp tile 32x64.
// A: raw f32 cp.async (double buffered, 128B rows SW128) -> per-kb convert
//    pass into fp16 tile AB (64B rows SW64). B: fp16 tiles identity cp.async.
// Epilogue packs fp16 into g_h2.
// ============================================================================
__global__ __launch_bounds__(256, 2)
void gemm_tc_kernel(const float* __restrict__ X)
{
    extern __shared__ char dsm[];
    const uint32_t base = (smem_u32(dsm) + 1023u) & ~1023u;
    const uint32_t RA0 = base;             // raw f32 A stages, 16KB each
    const uint32_t RA1 = base + 16384;
    const uint32_t AB  = base + 32768;     // fp16 A tile, 8KB
    const uint32_t BB0 = base + 40960;     // fp16 B stages, 8KB each
    const uint32_t BB1 = base + 49152;

    const int tid  = threadIdx.x;
    const int lane = tid & 31;
    const int wid  = tid >> 5;
    const int wm   = wid >> 1;             // 0..3
    const int wn   = wid & 1;              // 0..1
    const int brow = blockIdx.x * 128;

    // ---- raw-A cp.async assignment: 4 x 16B per thread (SW128 rows) ----
    uint32_t a_dst[4];
    const float* a_srcb[4];
    uint32_t a_sz[4];
    #pragma unroll
    for (int i = 0; i < 4; i++) {
        int idx = tid + i * 256;           // 0..1023
        int row = idx >> 3;                // 0..127
        int q   = idx & 7;                 // 16B group
        a_dst[i]  = (uint32_t)row * 128 + ((uint32_t)(q ^ (row & 7)) << 4);
        a_srcb[i] = X + (size_t)(brow + row) * KDIM + q * 4;
        a_sz[i]   = ((brow + row) < NNODES) ? 16u : 0u;
    }

    // ---- convert-pass assignment: 2 output 16B groups per thread ----
    uint32_t c_src[2][2], c_dst[2];
    #pragma unroll
    for (int i = 0; i < 2; i++) {
        int slot = tid + i * 256;          // 0..511
        int row  = slot >> 2;              // 0..127
        int og   = slot & 3;               // fp16 16B group (k 8og..8og+7)
        uint32_t rx = (uint32_t)(row & 7);
        c_src[i][0] = (uint32_t)row * 128 + (((uint32_t)(2 * og)     ^ rx) << 4);
        c_src[i][1] = (uint32_t)row * 128 + (((uint32_t)(2 * og + 1) ^ rx) << 4);
        c_dst[i]    = (uint32_t)row * 64 +
                      (((uint32_t)og ^ ((uint32_t)(row >> 1) & 3)) << 4);
    }

    // ---- ldmatrix address precompute (64B rows, SW64) ----
    uint32_t a_rb[2], a_rx[2];
    #pragma unroll
    for (int mf = 0; mf < 2; mf++) {
        uint32_t row = wm * 32 + mf * 16 + (lane & 15);
        a_rb[mf] = row * 64;
        a_rx[mf] = (row >> 1) & 3;
    }
    const uint32_t a_cbase = (uint32_t)(lane >> 4);
    uint32_t b_rb[4], b_rx[4];
    #pragma unroll
    for (int p = 0; p < 4; p++) {
        uint32_t n = wn * 64 + p * 16 + ((lane >> 4) << 3) + (lane & 7);
        b_rb[p] = n * 64;
        b_rx[p] = (n >> 1) & 3;
    }
    const uint32_t b_cbase = (uint32_t)((lane >> 3) & 1);

    float acc[2][8][4];
    #pragma unroll
    for (int mf = 0; mf < 2; mf++)
        #pragma unroll
        for (int nf = 0; nf < 8; nf++)
            #pragma unroll
            for (int j = 0; j < 4; j++) acc[mf][nf][j] = 0.f;

    // ---- prologue: stage kb=0 ----
    #pragma unroll
    for (int i = 0; i < 4; i++)
        cp_async16_z(RA0 + a_dst[i], a_srcb[i], a_sz[i]);
    #pragma unroll
    for (int i = 0; i < 2; i++) {
        int idx = tid + i * 256;           // 0..511 16B slots
        cp_async16(BB0 + idx * 16, g_Wb + idx * 4);
    }
    CP_COMMIT();

    for (int kb = 0; kb < KB_ITERS; kb++) {
        CP_WAIT(0);
        __syncthreads();   // RA/BB[cur] visible; AB free; prev compute done

        const uint32_t RA = (kb & 1) ? RA1 : RA0;
        const uint32_t BB = (kb & 1) ? BB1 : BB0;

        // ---- convert raw f32 -> fp16 tile AB ----
        #pragma unroll
        for (int i = 0; i < 2; i++) {
            uint4 a = lds128(RA + c_src[i][0]);
            uint4 b = lds128(RA + c_src[i][1]);
            uint4 o;
            o.x = f16x2_rn(__uint_as_float(a.x), __uint_as_float(a.y));
            o.y = f16x2_rn(__uint_as_float(a.z), __uint_as_float(a.w));
            o.z = f16x2_rn(__uint_as_float(b.x), __uint_as_float(b.y));
            o.w = f16x2_rn(__uint_as_float(b.z), __uint_as_float(b.w));
            sts128u(AB + c_dst[i], o);
        }
        __syncthreads();   // AB visible; RA[cur] reads done

        // ---- prefetch kb+1 (overlaps with compute below) ----
        if (kb + 1 < KB_ITERS) {
            const uint32_t nRA = (kb & 1) ? RA0 : RA1;
            const uint32_t nBB = (kb & 1) ? BB0 : BB1;
            const uint32_t* wb = g_Wb + (size_t)(kb + 1) * 2048;
            #pragma unroll
            for (int i = 0; i < 4; i++)
                cp_async16_z(nRA + a_dst[i], a_srcb[i] + (kb + 1) * BK, a_sz[i]);
            #pragma unroll
            for (int i = 0; i < 2; i++) {
                int idx = tid + i * 256;
                cp_async16(nBB + idx * 16, wb + idx * 4);
            }
            CP_COMMIT();
        }

        // ---- compute: 2 k16-steps, single fp16 pass ----
        #pragma unroll
        for (int s = 0; s < 2; s++) {
            uint32_t ah[2][4];
            #pragma unroll
            for (int mf = 0; mf < 2; mf++) {
                uint32_t g = (uint32_t)(s * 2) + a_cbase;
                uint32_t off = a_rb[mf] + ((g ^ a_rx[mf]) << 4);
                ldsm_x4(ah[mf][0], ah[mf][1], ah[mf][2], ah[mf][3], AB + off);
            }
            #pragma unroll
            for (int p = 0; p < 4; p++) {
                uint32_t g = (uint32_t)(s * 2) + b_cbase;
                uint32_t off = b_rb[p] + ((g ^ b_rx[p]) << 4);
                uint32_t bh[4];
                ldsm_x4(bh[0], bh[1], bh[2], bh[3], BB + off);
                #pragma unroll
                for (int j = 0; j < 2; j++) {
                    #pragma unroll
                    for (int mf = 0; mf < 2; mf++)
                        mma_fp16(acc[mf][p * 2 + j], ah[mf],
                                 bh[2 * j], bh[2 * j + 1]);
                }
            }
        }
    }

    // ---- epilogue: accum regs -> g_h2 (fp16 half2-packed) ----
    half2* H2 = (half2*)g_h2;
    #pragma unroll
    for (int mf = 0; mf < 2; mf++) {
        int row0 = brow + wm * 32 + mf * 16 + (lane >> 2);
        #pragma unroll
        for (int nf = 0; nf < 8; nf++) {
            int c2 = wn * 32 + nf * 4 + (lane & 3);   // half2 column index
            if (row0 < NNODES)
                H2[(size_t)row0 * 64 + c2] =
                    __floats2half2_rn(acc[mf][nf][0], acc[mf][nf][1]);
            if (row0 + 8 < NNODES)
                H2[(size_t)(row0 + 8) * 64 + c2] =
                    __floats2half2_rn(acc[mf][nf][2], acc[mf][nf][3]);
        }
    }
}

// ============================================================================
// CSR build kernels (unchanged)
// ============================================================================
__global__ void init_kernel()
{
    int i = blockIdx.x * blockDim.x + threadIdx.x;
    if (i < NNODES) { g_cnt[i] = 0; g_cursor[i] = 0; }
}

__global__ void hist_kernel(const int* __restrict__ dst)
{
    int e = blockIdx.x * blockDim.x + threadIdx.x;
    if (e < NEDGES) atomicAdd(&g_cnt[dst[e]], 1);
}

__global__ __launch_bounds__(SCAN_BLK)
void scan_blocks_kernel()
{
    __shared__ int sh[SCAN_BLK];
    const int t = threadIdx.x;
    const int i = blockIdx.x * SCAN_BLK + t;

    int v = (i < NNODES) ? g_cnt[i] : 0;
    if (i < NNODES) g_dinv[i] = rsqrtf((float)(v + 1));

    sh[t] = v;
    __syncthreads();
    #pragma unroll
    for (int d = 1; d < SCAN_BLK; d <<= 1) {
        int u = (t >= d) ? sh[t - d] : 0;
        __syncthreads();
        sh[t] += u;
        __syncthreads();
    }
    if (i < NNODES) g_off[i] = sh[t] - v;
    if (t == SCAN_BLK - 1) g_bsum[blockIdx.x] = sh[t];
}

__global__ __launch_bounds__(SCAN_BLK)
void scan_apply_kernel()
{
    __shared__ int red[SCAN_BLK];
    const int t = threadIdx.x;
    red[t] = (t < blockIdx.x) ? g_bsum[t] : 0;
    __syncthreads();
    #pragma unroll
    for (int d = SCAN_BLK / 2; d > 0; d >>= 1) {
        if (t < d) red[t] += red[t + d];
        __syncthreads();
    }
    const int base = red[0];
    const int i = blockIdx.x * SCAN_BLK + t;
    if (i < NNODES) g_off[i] += base;
    if (i == 0) g_off[NNODES] = NEDGES;
}

__global__ void fill_kernel(const int* __restrict__ src, const int* __restrict__ dst)
{
    int e = blockIdx.x * blockDim.x + threadIdx.x;
    if (e >= NEDGES) return;
    int d = dst[e];
    int p = atomicAdd(&g_cursor[d], 1);
    g_srcs[g_off[d] + p] = src[e];
}

// ============================================================================
// Aggregate + bias + PReLU. One warp per node; each lane owns 4 channels
// (one uint2 = 4 fp16 values).
// ============================================================================
__device__ __forceinline__ float4 h4_at(const uint2* h2, int node, int lane)
{
    uint2 v = h2[(size_t)node * 32 + lane];
    float2 f = __half22float2(*(const half2*)&v.x);
    float2 g = __half22float2(*(const half2*)&v.y);
    return make_float4(f.x, f.y, g.x, g.y);
}

__global__ __launch_bounds__(256)
void aggregate_kernel(const float* __restrict__ b,
                      const float* __restrict__ pw,
                      float* __restrict__ out)
{
    int gwarp = (blockIdx.x * blockDim.x + threadIdx.x) >> 5;
    int lane  = threadIdx.x & 31;
    if (gwarp >= NNODES) return;

    const uint2* h2 = (const uint2*)g_h2;
    const int n = gwarp;

    float di = g_dinv[n];
    float4 hn = h4_at(h2, n, lane);

    float4 acc = make_float4(0.f, 0.f, 0.f, 0.f);
    int s = g_off[n];
    int e = g_off[n + 1];

    int i = s;
    for (; i + 3 < e; i += 4) {
        int u0 = g_srcs[i];
        int u1 = g_srcs[i + 1];
        int u2 = g_srcs[i + 2];
        int u3 = g_srcs[i + 3];
        float w0 = g_dinv[u0], w1 = g_dinv[u1];
        float w2 = g_dinv[u2], w3 = g_dinv[u3];
        float4 v0 = h4_at(h2, u0, lane);
        float4 v1 = h4_at(h2, u1, lane);
        float4 v2 = h4_at(h2, u2, lane);
        float4 v3 = h4_at(h2, u3, lane);
        acc.x += v0.x * w0 + v1.x * w1 + v2.x * w2 + v3.x * w3;
        acc.y += v0.y * w0 + v1.y * w1 + v2.y * w2 + v3.y * w3;
        acc.z += v0.z * w0 + v1.z * w1 + v2.z * w2 + v3.z * w3;
        acc.w += v0.w * w0 + v1.w * w1 + v2.w * w2 + v3.w * w3;
    }
    for (; i < e; i++) {
        int u = g_srcs[i];
        float w = g_dinv[u];
        float4 v = h4_at(h2, u, lane);
        acc.x += v.x * w; acc.y += v.y * w; acc.z += v.z * w; acc.w += v.w * w;
    }

    float s2 = di * di;
    float4 bb = ((const float4*)b)[lane];
    float4 pp = ((const float4*)pw)[lane];
    float4 r;
    r.x = acc.x * di + hn.x * s2 + bb.x;
    r.y = acc.y * di + hn.y * s2 + bb.y;
    r.z = acc.z * di + hn.z * s2 + bb.z;
    r.w = acc.w * di + hn.w * s2 + bb.w;
    r.x = (r.x > 0.f) ? r.x : r.x * pp.x;
    r.y = (r.y > 0.f) ? r.y : r.y * pp.y;
    r.z = (r.z > 0.f) ? r.z : r.z * pp.z;
    r.w = (r.w > 0.f) ? r.w : r.w * pp.w;

    ((float4*)out)[(size_t)n * 32 + lane] = r;
}

// ============================================================================
// Launch
// ============================================================================
#define GEMM_DSMEM (57344 + 1024)

extern "C" void kernel_launch(void* const* d_in, const int* in_sizes, int n_in,
                              void* d_out, int out_size)
{
    const float* x  = (const float*)d_in[0];   // [50000, 512]
    const int*   ei = (const int*)  d_in[1];   // [2, 800000]
    const float* W  = (const float*)d_in[2];   // [512, 128]
    const float* b  = (const float*)d_in[3];   // [128]
    const float* pw = (const float*)d_in[4];   // [128]
    float* out = (float*)d_out;                // [50000, 128]

    const int* src = ei;
    const int* dst = ei + NEDGES;

    static cudaStream_t s2 = nullptr;
    static cudaEvent_t evFork = nullptr, evJoin = nullptr;
    if (s2 == nullptr) {
        cudaStreamCreateWithFlags(&s2, cudaStreamNonBlocking);
        cudaEventCreateWithFlags(&evFork, cudaEventDisableTiming);
        cudaEventCreateWithFlags(&evJoin, cudaEventDisableTiming);
        cudaFuncSetAttribute(gemm_tc_kernel,
                             cudaFuncAttributeMaxDynamicSharedMemorySize, GEMM_DSMEM);
    }

    // Fork: CSR-build chain on s2
    cudaEventRecord(evFork, 0);
    cudaStreamWaitEvent(s2, evFork, 0);

    init_kernel<<<(NNODES + 255) / 256, 256, 0, s2>>>();
    hist_kernel<<<(NEDGES + 255) / 256, 256, 0, s2>>>(dst);
    scan_blocks_kernel<<<N_SCAN_BLOCKS, SCAN_BLK, 0, s2>>>();
    scan_apply_kernel<<<N_SCAN_BLOCKS, SCAN_BLK, 0, s2>>>();
    fill_kernel<<<(NEDGES + 255) / 256, 256, 0, s2>>>(src, dst);
    cudaEventRecord(evJoin, s2);

    // Main stream: W -> fp16 pack, then fp16 tensor-core GEMM
    wprep_kernel<<<(WB_U32 + 255) / 256, 256>>>(W);
    gemm_tc_kernel<<<N_TILES, 256, GEMM_DSMEM>>>(x);

    // Join, then aggregate (needs both h and CSR)
    cudaStreamWaitEvent(0, evJoin, 0);
    aggregate_kernel<<<(NNODES * 32 + 255) / 256, 256>>>(b, pw, out);
}

// round 9
// speedup vs baseline: 3.3932x; 1.0861x over previous
#include <cuda_runtime.h>
#include <cuda_bf16.h>
#include <cuda_fp16.h>
#include <stdint.h>

// Problem constants (fixed by the reference)
#define NNODES 50000
#define NEDGES 800000
#define KDIM   512
#define HDIM   128

#define SCAN_BLK 256
#define N_SCAN_BLOCKS ((NNODES + SCAN_BLK - 1) / SCAN_BLK)   // 196

#define BK 32
#define KB_ITERS (KDIM / BK)           // 16
#define N_TILES ((NNODES + 127) / 128) // 391
#define WB_U32  (KB_ITERS * 2048)      // W fp16 tiles: 16 x 8KB = 32K u32

// ---------------- device scratch (no allocs allowed) ----------------
__device__ uint32_t g_h2[NNODES * 64];      // h = x @ W, fp16 half2-packed
__device__ int      g_cnt[NNODES];          // zeroed by scan for next run
__device__ int      g_off[NNODES + 1];
__device__ int      g_cursor[NNODES];       // zeroed by scan for next run
__device__ int      g_srcs[NEDGES];
__device__ float    g_dinv[NNODES];
__device__ int      g_bsum[N_SCAN_BLOCKS];
__device__ int      g_done;                 // grid-barrier counter (reset by hist)
// W as fp16, per-kb tiles [n=128][64B row: k0-31], SW64-swizzled:
__device__ uint32_t g_Wb[WB_U32];

// ======================= PTX helpers (baseline compute_103-safe) ==========
__device__ __forceinline__ uint32_t smem_u32(const void* p) {
    uint32_t a;
    asm("{ .reg .u64 t; cvta.to.shared.u64 t, %1; cvt.u32.u64 %0, t; }"
        : "=r"(a) : "l"(p));
    return a;
}
__device__ __forceinline__ uint32_t sw64(uint32_t off) {
    return off ^ ((off >> 3) & 0x30);
}
__device__ __forceinline__ void ldsm_x4(uint32_t& r0, uint32_t& r1,
                                        uint32_t& r2, uint32_t& r3, uint32_t addr) {
    asm volatile("ldmatrix.sync.aligned.m8n8.x4.shared.b16 {%0,%1,%2,%3}, [%4];"
        : "=r"(r0), "=r"(r1), "=r"(r2), "=r"(r3) : "r"(addr));
}
__device__ __forceinline__ void mma_fp16(float* c, const uint32_t* a,
                                         uint32_t b0, uint32_t b1) {
    asm volatile(
        "mma.sync.aligned.m16n8k16.row.col.f32.f16.f16.f32 "
        "{%0,%1,%2,%3}, {%4,%5,%6,%7}, {%8,%9}, {%0,%1,%2,%3};"
        : "+f"(c[0]), "+f"(c[1]), "+f"(c[2]), "+f"(c[3])
        : "r"(a[0]), "r"(a[1]), "r"(a[2]), "r"(a[3]), "r"(b0), "r"(b1));
}
__device__ __forceinline__ void cp_async16(uint32_t smem_dst, const void* gsrc) {
    asm volatile("cp.async.cg.shared.global [%0], [%1], 16;"
        :: "r"(smem_dst), "l"(gsrc) : "memory");
}
__device__ __forceinline__ void cp_async16_z(uint32_t smem_dst, const void* gsrc,
                                             uint32_t srcsz) {
    asm volatile("cp.async.cg.shared.global [%0], [%1], 16, %2;"
        :: "r"(smem_dst), "l"(gsrc), "r"(srcsz) : "memory");
}
#define CP_COMMIT() asm volatile("cp.async.commit_group;" ::: "memory")
#define CP_WAIT(n)  asm volatile("cp.async.wait_group %0;" :: "n"(n) : "memory")
__device__ __forceinline__ uint4 lds128(uint32_t a) {
    uint4 v;
    asm volatile("ld.shared.v4.u32 {%0,%1,%2,%3}, [%4];"
        : "=r"(v.x), "=r"(v.y), "=r"(v.z), "=r"(v.w) : "r"(a));
    return v;
}
__device__ __forceinline__ void sts128u(uint32_t a, uint4 v) {
    asm volatile("st.shared.v4.u32 [%0], {%1,%2,%3,%4};"
        :: "r"(a), "r"(v.x), "r"(v.y), "r"(v.z), "r"(v.w) : "memory");
}
__device__ __forceinline__ uint32_t f16x2_rn(float lo, float hi) {
    uint32_t r;
    asm("cvt.rn.f16x2.f32 %0, %1, %2;" : "=r"(r) : "f"(hi), "f"(lo));
    return r;
}

// ============================================================================
// Kernel 0: W -> fp16 tiles, per-kb [n=128][64B: k0-31], SW64-swizzled.
// ============================================================================
__global__ __launch_bounds__(256)
void wprep_kernel(const float* __restrict__ W)
{
    int o = blockIdx.x * blockDim.x + threadIdx.x;
    if (o >= WB_U32) return;
    int kb = o >> 11;
    uint32_t byte = (o & 2047) * 4;
    uint32_t un = sw64(byte);
    int n = un >> 6;
    int i = (un & 63) >> 2;
    int k0 = kb * BK + 2 * i;
    float w0 = W[(size_t)k0 * HDIM + n];
    float w1 = W[(size_t)(k0 + 1) * HDIM + n];
    g_Wb[o] = f16x2_rn(w0, w1);
}

// ============================================================================
// Kernel 1: fp16 GEMM via mma.sync m16n8k16 (f32 accumulate).
// CTA 128x128, 256 threads, warp tile 32x64. 3-stage cp.async pipeline.
// ============================================================================
__global__ __launch_bounds__(256, 2)
void gemm_tc_kernel(const float* __restrict__ X)
{
    extern __shared__ char dsm[];
    const uint32_t base = (smem_u32(dsm) + 1023u) & ~1023u;
    uint32_t RA[3] = { base, base + 16384, base + 32768 };       // raw f32 stages
    uint32_t BB[3] = { base + 49152, base + 57344, base + 65536 }; // fp16 W stages
    const uint32_t AB = base + 73728;                             // fp16 A tile

    const int tid  = threadIdx.x;
    const int lane = tid & 31;
    const int wid  = tid >> 5;
    const int wm   = wid >> 1;
    const int wn   = wid & 1;
    const int brow = blockIdx.x * 128;

    // ---- raw-A cp.async assignment: 4 x 16B per thread (SW128 rows) ----
    uint32_t a_dst[4];
    const float* a_srcb[4];
    uint32_t a_sz[4];
    #pragma unroll
    for (int i = 0; i < 4; i++) {
        int idx = tid + i * 256;
        int row = idx >> 3;
        int q   = idx & 7;
        a_dst[i]  = (uint32_t)row * 128 + ((uint32_t)(q ^ (row & 7)) << 4);
        a_srcb[i] = X + (size_t)(brow + row) * KDIM + q * 4;
        a_sz[i]   = ((brow + row) < NNODES) ? 16u : 0u;
    }

    // ---- convert-pass assignment: 2 output 16B groups per thread ----
    uint32_t c_src[2][2], c_dst[2];
    #pragma unroll
    for (int i = 0; i < 2; i++) {
        int slot = tid + i * 256;
        int row  = slot >> 2;
        int og   = slot & 3;
        uint32_t rx = (uint32_t)(row & 7);
        c_src[i][0] = (uint32_t)row * 128 + (((uint32_t)(2 * og)     ^ rx) << 4);
        c_src[i][1] = (uint32_t)row * 128 + (((uint32_t)(2 * og + 1) ^ rx) << 4);
        c_dst[i]    = (uint32_t)row * 64 +
                      (((uint32_t)og ^ ((uint32_t)(row >> 1) & 3)) << 4);
    }

    // ---- ldmatrix address precompute (64B rows, SW64) ----
    uint32_t a_rb[2], a_rx[2];
    #pragma unroll
    for (int mf = 0; mf < 2; mf++) {
        uint32_t row = wm * 32 + mf * 16 + (lane & 15);
        a_rb[mf] = row * 64;
        a_rx[mf] = (row >> 1) & 3;
    }
    const uint32_t a_cbase = (uint32_t)(lane >> 4);
    uint32_t b_rb[4], b_rx[4];
    #pragma unroll
    for (int p = 0; p < 4; p++) {
        uint32_t n = wn * 64 + p * 16 + ((lane >> 4) << 3) + (lane & 7);
        b_rb[p] = n * 64;
        b_rx[p] = (n >> 1) & 3;
    }
    const uint32_t b_cbase = (uint32_t)((lane >> 3) & 1);

    float acc[2][8][4];
    #pragma unroll
    for (int mf = 0; mf < 2; mf++)
        #pragma unroll
        for (int nf = 0; nf < 8; nf++)
            #pragma unroll
            for (int j = 0; j < 4; j++) acc[mf][nf][j] = 0.f;

    // ---- stage helper (stage s into buffer s%3), one commit per stage ----
    auto stage = [&](int s) {
        uint32_t ra = RA[s % 3], bb = BB[s % 3];
        const uint32_t* wb = g_Wb + (size_t)s * 2048;
        #pragma unroll
        for (int i = 0; i < 4; i++)
            cp_async16_z(ra + a_dst[i], a_srcb[i] + s * BK, a_sz[i]);
        #pragma unroll
        for (int i = 0; i < 2; i++) {
            int idx = tid + i * 256;
            cp_async16(bb + idx * 16, wb + idx * 4);
        }
        CP_COMMIT();
    };

    // ---- prologue: stages 0 and 1 in flight ----
    stage(0);
    stage(1);

    for (int kb = 0; kb < KB_ITERS; kb++) {
        if (kb + 1 < KB_ITERS) { CP_WAIT(1); } else { CP_WAIT(0); }
        __syncthreads();   // stage kb visible; AB free (prev compute done)

        const uint32_t RAc = RA[kb % 3];
        const uint32_t BBc = BB[kb % 3];

        // ---- convert raw f32 -> fp16 tile AB ----
        #pragma unroll
        for (int i = 0; i < 2; i++) {
            uint4 a = lds128(RAc + c_src[i][0]);
            uint4 b = lds128(RAc + c_src[i][1]);
            uint4 o;
            o.x = f16x2_rn(__uint_as_float(a.x), __uint_as_float(a.y));
            o.y = f16x2_rn(__uint_as_float(a.z), __uint_as_float(a.w));
            o.z = f16x2_rn(__uint_as_float(b.x), __uint_as_float(b.y));
            o.w = f16x2_rn(__uint_as_float(b.z), __uint_as_float(b.w));
            sts128u(AB + c_dst[i], o);
        }
        __syncthreads();   // AB visible; RA[kb] reads done

        // ---- keep 2 stages in flight ----
        if (kb + 2 < KB_ITERS) stage(kb + 2);

        // ---- compute: 2 k16-steps, single fp16 pass ----
        #pragma unroll
        for (int s = 0; s < 2; s++) {
            uint32_t ah[2][4];
            #pragma unroll
            for (int mf = 0; mf < 2; mf++) {
                uint32_t g = (uint32_t)(s * 2) + a_cbase;
                uint32_t off = a_rb[mf] + ((g ^ a_rx[mf]) << 4);
                ldsm_x4(ah[mf][0], ah[mf][1], ah[mf][2], ah[mf][3], AB + off);
            }
            #pragma unroll
            for (int p = 0; p < 4; p++) {
                uint32_t g = (uint32_t)(s * 2) + b_cbase;
                uint32_t off = b_rb[p] + ((g ^ b_rx[p]) << 4);
                uint32_t bh[4];
                ldsm_x4(bh[0], bh[1], bh[2], bh[3], BBc + off);
                #pragma unroll
                for (int j = 0; j < 2; j++) {
                    #pragma unroll
                    for (int mf = 0; mf < 2; mf++)
                        mma_fp16(acc[mf][p * 2 + j], ah[mf],
                                 bh[2 * j], bh[2 * j + 1]);
                }
            }
        }
    }

    // ---- epilogue: accum regs -> g_h2 (fp16 half2-packed) ----
    half2* H2 = (half2*)g_h2;
    #pragma unroll
    for (int mf = 0; mf < 2; mf++) {
        int row0 = brow + wm * 32 + mf * 16 + (lane >> 2);
        #pragma unroll
        for (int nf = 0; nf < 8; nf++) {
            int c2 = wn * 32 + nf * 4 + (lane & 3);
            if (row0 < NNODES)
                H2[(size_t)row0 * 64 + c2] =
                    __floats2half2_rn(acc[mf][nf][0], acc[mf][nf][1]);
            if (row0 + 8 < NNODES)
                H2[(size_t)(row0 + 8) * 64 + c2] =
                    __floats2half2_rn(acc[mf][nf][2], acc[mf][nf][3]);
        }
    }
}

// ============================================================================
// Kernel 2: histogram (also resets the scan grid-barrier counter)
// ============================================================================
__global__ void hist_kernel(const int* __restrict__ dst)
{
    int e = blockIdx.x * blockDim.x + threadIdx.x;
    if (e == 0) g_done = 0;
    if (e < NEDGES) atomicAdd(&g_cnt[dst[e]], 1);
}

// ============================================================================
// Kernel 3: fused scan (local scan + grid barrier + apply). Also computes
// dinv and self-cleans g_cnt / g_cursor for the next call.
// ============================================================================
__global__ __launch_bounds__(SCAN_BLK)
void scan_kernel()
{
    __shared__ int sh[SCAN_BLK];
    __shared__ int red[SCAN_BLK];
    const int t   = threadIdx.x;
    const int blk = blockIdx.x;
    const int i   = blk * SCAN_BLK + t;

    int v = 0;
    if (i < NNODES) {
        v = g_cnt[i];
        g_dinv[i]   = rsqrtf((float)(v + 1));
        g_cnt[i]    = 0;   // self-clean for next run
        g_cursor[i] = 0;   // fill's cursors start at 0
    }

    sh[t] = v;
    __syncthreads();
    #pragma unroll
    for (int d = 1; d < SCAN_BLK; d <<= 1) {
        int u = (t >= d) ? sh[t - d] : 0;
        __syncthreads();
        sh[t] += u;
        __syncthreads();
    }
    int local_excl = sh[t] - v;

    if (t == SCAN_BLK - 1) g_bsum[blk] = sh[t];
    __threadfence();
    __syncthreads();
    if (t == 0) {
        atomicAdd(&g_done, 1);
        volatile int* dp = &g_done;
        while (*dp < N_SCAN_BLOCKS) { }
    }
    __syncthreads();
    __threadfence();

    red[t] = (t < blk) ? g_bsum[t] : 0;    // blk <= 195 < 256
    __syncthreads();
    #pragma unroll
    for (int d = SCAN_BLK / 2; d > 0; d >>= 1) {
        if (t < d) red[t] += red[t + d];
        __syncthreads();
    }
    if (i < NNODES) g_off[i] = local_excl + red[0];
    if (i == 0) g_off[NNODES] = NEDGES;
}

// ============================================================================
// Kernel 4: fill CSR
// ============================================================================
__global__ void fill_kernel(const int* __restrict__ src, const int* __restrict__ dst)
{
    int e = blockIdx.x * blockDim.x + threadIdx.x;
    if (e >= NEDGES) return;
    int d = dst[e];
    int p = atomicAdd(&g_cursor[d], 1);
    g_srcs[g_off[d] + p] = src[e];
}

// ============================================================================
// Kernel 5: aggregate + bias + PReLU. One warp per node, fp16 gather.
// ============================================================================
__device__ __forceinline__ float4 h4_at(const uint2* h2, int node, int lane)
{
    uint2 v = h2[(size_t)node * 32 + lane];
    float2 f = __half22float2(*(const half2*)&v.x);
    float2 g = __half22float2(*(const half2*)&v.y);
    return make_float4(f.x, f.y, g.x, g.y);
}

__global__ __launch_bounds__(256)
void aggregate_kernel(const float* __restrict__ b,
                      const float* __restrict__ pw,
                      float* __restrict__ out)
{
    int gwarp = (blockIdx.x * blockDim.x + threadIdx.x) >> 5;
    int lane  = threadIdx.x & 31;
    if (gwarp >= NNODES) return;

    const uint2* h2 = (const uint2*)g_h2;
    const int n = gwarp;

    float di = g_dinv[n];
    float4 hn = h4_at(h2, n, lane);

    float4 acc = make_float4(0.f, 0.f, 0.f, 0.f);
    int s = g_off[n];
    int e = g_off[n + 1];

    int i = s;
    for (; i + 3 < e; i += 4) {
        int u0 = g_srcs[i];
        int u1 = g_srcs[i + 1];
        int u2 = g_srcs[i + 2];
        int u3 = g_srcs[i + 3];
        float w0 = g_dinv[u0], w1 = g_dinv[u1];
        float w2 = g_dinv[u2], w3 = g_dinv[u3];
        float4 v0 = h4_at(h2, u0, lane);
        float4 v1 = h4_at(h2, u1, lane);
        float4 v2 = h4_at(h2, u2, lane);
        float4 v3 = h4_at(h2, u3, lane);
        acc.x += v0.x * w0 + v1.x * w1 + v2.x * w2 + v3.x * w3;
        acc.y += v0.y * w0 + v1.y * w1 + v2.y * w2 + v3.y * w3;
        acc.z += v0.z * w0 + v1.z * w1 + v2.z * w2 + v3.z * w3;
        acc.w += v0.w * w0 + v1.w * w1 + v2.w * w2 + v3.w * w3;
    }
    for (; i < e; i++) {
        int u = g_srcs[i];
        float w = g_dinv[u];
        float4 v = h4_at(h2, u, lane);
        acc.x += v.x * w; acc.y += v.y * w; acc.z += v.z * w; acc.w += v.w * w;
    }

    float s2 = di * di;
    float4 bb = ((const float4*)b)[lane];
    float4 pp = ((const float4*)pw)[lane];
    float4 r;
    r.x = acc.x * di + hn.x * s2 + bb.x;
    r.y = acc.y * di + hn.y * s2 + bb.y;
    r.z = acc.z * di + hn.z * s2 + bb.z;
    r.w = acc.w * di + hn.w * s2 + bb.w;
    r.x = (r.x > 0.f) ? r.x : r.x * pp.x;
    r.y = (r.y > 0.f) ? r.y : r.y * pp.y;
    r.z = (r.z > 0.f) ? r.z : r.z * pp.z;
    r.w = (r.w > 0.f) ? r.w : r.w * pp.w;

    ((float4*)out)[(size_t)n * 32 + lane] = r;
}

// ============================================================================
// Launch: 6 kernel nodes total.
// ============================================================================
#define GEMM_DSMEM (81920 + 2048)

extern "C" void kernel_launch(void* const* d_in, const int* in_sizes, int n_in,
                              void* d_out, int out_size)
{
    const float* x  = (const float*)d_in[0];   // [50000, 512]
    const int*   ei = (const int*)  d_in[1];   // [2, 800000]
    const float* W  = (const float*)d_in[2];   // [512, 128]
    const float* b  = (const float*)d_in[3];   // [128]
    const float* pw = (const float*)d_in[4];   // [128]
    float* out = (float*)d_out;                // [50000, 128]

    const int* src = ei;
    const int* dst = ei + NEDGES;

    static cudaStream_t s2 = nullptr;
    static cudaEvent_t evFork = nullptr, evJoin = nullptr;
    if (s2 == nullptr) {
        cudaStreamCreateWithFlags(&s2, cudaStreamNonBlocking);
        cudaEventCreateWithFlags(&evFork, cudaEventDisableTiming);
        cudaEventCreateWithFlags(&evJoin, cudaEventDisableTiming);
        cudaFuncSetAttribute(gemm_tc_kernel,
                             cudaFuncAttributeMaxDynamicSharedMemorySize, GEMM_DSMEM);
    }

    // Fork: CSR-build chain on s2
    cudaEventRecord(evFork, 0);
    cudaStreamWaitEvent(s2, evFork, 0);

    hist_kernel<<<(NEDGES + 255) / 256, 256, 0, s2>>>(dst);
    scan_kernel<<<N_SCAN_BLOCKS, SCAN_BLK, 0, s2>>>();
    fill_kernel<<<(NEDGES + 255) / 256, 256, 0, s2>>>(src, dst);
    cudaEventRecord(evJoin, s2);

    // Main stream: W -> fp16 pack, then fp16 tensor-core GEMM
    wprep_kernel<<<(WB_U32 + 255) / 256, 256>>>(W);
    gemm_tc_kernel<<<N_TILES, 256, GEMM_DSMEM>>>(x);

    // Join, then aggregate (needs both h and CSR)
    cudaStreamWaitEvent(0, evJoin, 0);
    aggregate_kernel<<<(NNODES * 32 + 255) / 256, 256>>>(b, pw, out);
}